// round 1
// baseline (speedup 1.0000x reference)
#include <cuda_runtime.h>
#include <cuda_bf16.h>
#include <math.h>

// ---------------- problem constants ----------------
#define BB 64
#define NTOK 1280      // N (keys)
#define NQ 320         // N_ (queries)
#define CIN 256
#define CKV 768        // NH_KD + DH
#define CQ 256         // NH_KD
#define DHD 512        // DH
#define COUT 512
#define NH 8
#define KD 32
#define DV 64
#define EPSBN 1e-5f
#define SCALE_ATTN 0.17677669529663687f  // 32^-0.5

#define M_KV (BB*NTOK)   // 81920
#define M_Q  (BB*NQ)     // 20480

// ---------------- device scratch (no allocations allowed) ----------------
__device__ float g_sKV[(size_t)M_KV * CKV];     // raw KV gemm output
__device__ float g_sXsub[(size_t)M_Q * CIN];    // gathered subsampled x
__device__ float g_sQ[(size_t)M_Q * CQ];        // raw Q gemm output
__device__ float g_sO[(size_t)M_Q * DHD];       // hard_swish(attention output)
__device__ float g_sP[(size_t)M_Q * COUT];      // raw out-proj gemm
__device__ float g_psum[CKV * 32];
__device__ float g_psq[CKV * 32];
__device__ float g_aKV[CKV], g_shKV[CKV];
__device__ float g_aQ[CQ],  g_shQ[CQ];
__device__ float g_aP[COUT], g_shP[COUT];

// ---------------- gather subsampled query tokens ----------------
// idx over M_Q * (CIN/4) float4s
__global__ void gather_q_kernel(const float* __restrict__ x, float* __restrict__ xs)
{
    int idx = blockIdx.x * blockDim.x + threadIdx.x;   // 20480*64 = 1,310,720
    int row = idx >> 6;          // b*320 + i
    int f   = idx & 63;          // float4 within 256-channel row
    int b = row / NQ;
    int i = row - b * NQ;
    int src;
    if (i < 256) {              // search region: 16x16 from 32x32
        int r = i >> 4, c = i & 15;
        src = (r * 2) * 32 + c * 2;
    } else {                    // template: 8x8 from 16x16
        int j = i - 256;
        int r = j >> 3, c = j & 7;
        src = 1024 + (r * 2) * 16 + c * 2;
    }
    const float4* xp = (const float4*)x;
    float4* op = (float4*)xs;
    op[(size_t)row * 64 + f] = xp[((size_t)b * NTOK + src) * 64 + f];
}

// ---------------- classic 128x128x16 SGEMM, C = A(MxK) * B(NxK)^T ----------------
__global__ __launch_bounds__(256)
void sgemm_nt(const float* __restrict__ A, const float* __restrict__ B,
              float* __restrict__ C, int M, int N, int K)
{
    const int BM = 128, BN = 128, BK = 16;
    __shared__ float As[BK][BM];
    __shared__ float Bs[BK][BN];

    int tid = threadIdx.x;
    int bm = blockIdx.y * BM;
    int bn = blockIdx.x * BN;
    int tx = tid & 15;          // 0..15
    int ty = tid >> 4;          // 0..15

    int lrow = tid >> 2;        // 0..63
    int lc4  = tid & 3;         // float4 index within 16-wide k slab

    float acc[8][8];
#pragma unroll
    for (int i = 0; i < 8; i++)
#pragma unroll
        for (int j = 0; j < 8; j++) acc[i][j] = 0.f;

    for (int k0 = 0; k0 < K; k0 += BK) {
        float4 a0 = ((const float4*)(A + (size_t)(bm + lrow) * K + k0))[lc4];
        float4 a1 = ((const float4*)(A + (size_t)(bm + lrow + 64) * K + k0))[lc4];
        float4 b0 = ((const float4*)(B + (size_t)(bn + lrow) * K + k0))[lc4];
        float4 b1 = ((const float4*)(B + (size_t)(bn + lrow + 64) * K + k0))[lc4];

        __syncthreads();
        int kc = lc4 * 4;
        As[kc + 0][lrow] = a0.x; As[kc + 1][lrow] = a0.y;
        As[kc + 2][lrow] = a0.z; As[kc + 3][lrow] = a0.w;
        As[kc + 0][lrow + 64] = a1.x; As[kc + 1][lrow + 64] = a1.y;
        As[kc + 2][lrow + 64] = a1.z; As[kc + 3][lrow + 64] = a1.w;
        Bs[kc + 0][lrow] = b0.x; Bs[kc + 1][lrow] = b0.y;
        Bs[kc + 2][lrow] = b0.z; Bs[kc + 3][lrow] = b0.w;
        Bs[kc + 0][lrow + 64] = b1.x; Bs[kc + 1][lrow + 64] = b1.y;
        Bs[kc + 2][lrow + 64] = b1.z; Bs[kc + 3][lrow + 64] = b1.w;
        __syncthreads();

#pragma unroll
        for (int k = 0; k < BK; k++) {
            float ra[8], rb[8];
#pragma unroll
            for (int i = 0; i < 8; i++) ra[i] = As[k][ty * 8 + i];
#pragma unroll
            for (int j = 0; j < 8; j++) rb[j] = Bs[k][tx * 8 + j];
#pragma unroll
            for (int i = 0; i < 8; i++)
#pragma unroll
                for (int j = 0; j < 8; j++) acc[i][j] += ra[i] * rb[j];
        }
    }

#pragma unroll
    for (int i = 0; i < 8; i++) {
        float* crow = C + (size_t)(bm + ty * 8 + i) * N + bn + tx * 8;
        ((float4*)crow)[0] = make_float4(acc[i][0], acc[i][1], acc[i][2], acc[i][3]);
        ((float4*)crow)[1] = make_float4(acc[i][4], acc[i][5], acc[i][6], acc[i][7]);
    }
}

// ---------------- BN stats: stage 1 (deterministic partials) ----------------
// grid (C/32, 32), block (32,8)
__global__ void bn_partial(const float* __restrict__ Y, int M, int C,
                           float* __restrict__ psum, float* __restrict__ psq)
{
    int col = blockIdx.x * 32 + threadIdx.x;
    int chunk = M / 32;
    int r0 = blockIdx.y * chunk;
    float s = 0.f, s2 = 0.f;
    for (int r = r0 + threadIdx.y; r < r0 + chunk; r += 8) {
        float v = Y[(size_t)r * C + col];
        s += v; s2 += v * v;
    }
    __shared__ float ssum[8][32];
    __shared__ float ssq[8][32];
    ssum[threadIdx.y][threadIdx.x] = s;
    ssq[threadIdx.y][threadIdx.x] = s2;
    __syncthreads();
    if (threadIdx.y == 0) {
        float ts = 0.f, ts2 = 0.f;
#pragma unroll
        for (int y = 0; y < 8; y++) { ts += ssum[y][threadIdx.x]; ts2 += ssq[y][threadIdx.x]; }
        psum[blockIdx.y * C + col] = ts;
        psq[blockIdx.y * C + col]  = ts2;
    }
}

// stage 2: one block, C threads -> affine scale/shift
__global__ void bn_finalize(const float* __restrict__ psum, const float* __restrict__ psq,
                            const float* __restrict__ g, const float* __restrict__ bta,
                            int C, float invM, float* __restrict__ a, float* __restrict__ sh)
{
    int c = threadIdx.x;
    if (c >= C) return;
    float s = 0.f, s2 = 0.f;
    for (int r = 0; r < 32; r++) { s += psum[r * C + c]; s2 += psq[r * C + c]; }
    float mean = s * invM;
    float var = s2 * invM - mean * mean;
    float aa = g[c] * rsqrtf(var + EPSBN);
    a[c] = aa;
    sh[c] = bta[c] - mean * aa;
}

// ---------------- attention: flash-style, 1 thread = 1 query ----------------
// grid (5 q-tiles, 8 heads, 64 batch), 64 threads
__global__ __launch_bounds__(64)
void attn_kernel(const float* __restrict__ Q, const float* __restrict__ KV,
                 const float* __restrict__ aQ, const float* __restrict__ shQ,
                 const float* __restrict__ aKV, const float* __restrict__ shKV,
                 float* __restrict__ O)
{
    int t = threadIdx.x;
    int qt = blockIdx.x, h = blockIdx.y, b = blockIdx.z;
    int nq = qt * 64 + t;

    __shared__ float4 ks[64][8];    // 64 keys x 32 k-dims
    __shared__ float4 vs[64][16];   // 64 keys x 64 v-dims
    __shared__ float aC[96], sC[96];

    for (int i = t; i < 96; i += 64) {
        aC[i] = aKV[h * 96 + i];
        sC[i] = shKV[h * 96 + i];
    }

    // load + BN-affine + pre-scale q
    float q[32];
    {
        const float* qrow = Q + ((size_t)(b * NQ + nq)) * CQ + h * KD;
#pragma unroll
        for (int j = 0; j < 32; j++)
            q[j] = (qrow[j] * aQ[h * KD + j] + shQ[h * KD + j]) * SCALE_ATTN;
    }

    float o[64];
#pragma unroll
    for (int d = 0; d < 64; d++) o[d] = 0.f;
    float l = 0.f;

    for (int kt = 0; kt < NTOK / 64; kt++) {
        __syncthreads();
        // cooperative tile load with BN affine folded in: 64 rows x 24 float4
        for (int idx = t; idx < 64 * 24; idx += 64) {
            int row = idx / 24, f = idx % 24;
            const float4* rp = (const float4*)(KV + ((size_t)(b * NTOK + kt * 64 + row)) * CKV + h * 96);
            float4 v = rp[f];
            int c = f * 4;
            v.x = v.x * aC[c + 0] + sC[c + 0];
            v.y = v.y * aC[c + 1] + sC[c + 1];
            v.z = v.z * aC[c + 2] + sC[c + 2];
            v.w = v.w * aC[c + 3] + sC[c + 3];
            if (f < 8) ks[row][f] = v; else vs[row][f - 8] = v;
        }
        __syncthreads();

#pragma unroll 2
        for (int kk = 0; kk < 64; kk++) {
            float s = 0.f;
#pragma unroll
            for (int f = 0; f < 8; f++) {
                float4 k4 = ks[kk][f];
                s += q[f * 4 + 0] * k4.x + q[f * 4 + 1] * k4.y
                   + q[f * 4 + 2] * k4.z + q[f * 4 + 3] * k4.w;
            }
            // scores are O(1) (BN'd inputs): exp is safe without max subtraction
            float p = __expf(s);
            l += p;
#pragma unroll
            for (int f = 0; f < 16; f++) {
                float4 v4 = vs[kk][f];
                o[f * 4 + 0] += p * v4.x;
                o[f * 4 + 1] += p * v4.y;
                o[f * 4 + 2] += p * v4.z;
                o[f * 4 + 3] += p * v4.w;
            }
        }
    }

    float inv = 1.f / l;
    float* orow = O + ((size_t)(b * NQ + nq)) * DHD + h * DV;
#pragma unroll
    for (int f = 0; f < 16; f++) {
        float4 r;
        float v0 = o[f * 4 + 0] * inv, v1 = o[f * 4 + 1] * inv;
        float v2 = o[f * 4 + 2] * inv, v3 = o[f * 4 + 3] * inv;
        // fused hard_swish: x * clamp(x+3,0,6)/6
        r.x = v0 * fminf(fmaxf(v0 + 3.f, 0.f), 6.f) * (1.f / 6.f);
        r.y = v1 * fminf(fmaxf(v1 + 3.f, 0.f), 6.f) * (1.f / 6.f);
        r.z = v2 * fminf(fmaxf(v2 + 3.f, 0.f), 6.f) * (1.f / 6.f);
        r.w = v3 * fminf(fmaxf(v3 + 3.f, 0.f), 6.f) * (1.f / 6.f);
        ((float4*)orow)[f] = r;
    }
}

// ---------------- final BN-affine into d_out ----------------
__global__ void apply_affine_out(const float* __restrict__ Y,
                                 const float* __restrict__ a, const float* __restrict__ sh,
                                 float* __restrict__ out)
{
    int idx = blockIdx.x * blockDim.x + threadIdx.x;  // over M_Q*COUT/4
    int c4 = idx & 127;                               // COUT/4 = 128
    float4 y = ((const float4*)Y)[idx];
    float4 aa = ((const float4*)a)[c4];
    float4 ss = ((const float4*)sh)[c4];
    float4 r;
    r.x = y.x * aa.x + ss.x;
    r.y = y.y * aa.y + ss.y;
    r.z = y.z * aa.z + ss.z;
    r.w = y.w * aa.w + ss.w;
    ((float4*)out)[idx] = r;
}

// ---------------- launch ----------------
extern "C" void kernel_launch(void* const* d_in, const int* in_sizes, int n_in,
                              void* d_out, int out_size)
{
    const float* x   = (const float*)d_in[0];
    const float* Wkv = (const float*)d_in[1];
    const float* gkv = (const float*)d_in[2];
    const float* bkv = (const float*)d_in[3];
    const float* Wq  = (const float*)d_in[4];
    const float* gq  = (const float*)d_in[5];
    const float* bq  = (const float*)d_in[6];
    const float* Wp  = (const float*)d_in[7];
    const float* gp  = (const float*)d_in[8];
    const float* bp  = (const float*)d_in[9];
    float* out = (float*)d_out;

    float *sKV, *sXsub, *sQ, *sO, *sP, *psum, *psq;
    float *aKV, *shKV, *aQ, *shQ, *aP, *shP;
    cudaGetSymbolAddress((void**)&sKV,   g_sKV);
    cudaGetSymbolAddress((void**)&sXsub, g_sXsub);
    cudaGetSymbolAddress((void**)&sQ,    g_sQ);
    cudaGetSymbolAddress((void**)&sO,    g_sO);
    cudaGetSymbolAddress((void**)&sP,    g_sP);
    cudaGetSymbolAddress((void**)&psum,  g_psum);
    cudaGetSymbolAddress((void**)&psq,   g_psq);
    cudaGetSymbolAddress((void**)&aKV,   g_aKV);
    cudaGetSymbolAddress((void**)&shKV,  g_shKV);
    cudaGetSymbolAddress((void**)&aQ,    g_aQ);
    cudaGetSymbolAddress((void**)&shQ,   g_shQ);
    cudaGetSymbolAddress((void**)&aP,    g_aP);
    cudaGetSymbolAddress((void**)&shP,   g_shP);

    // 1. gather subsampled query tokens
    gather_q_kernel<<<(M_Q * (CIN / 4)) / 256, 256>>>(x, sXsub);

    // 2. KV and Q projections
    sgemm_nt<<<dim3(CKV / 128, M_KV / 128), 256>>>(x, Wkv, sKV, M_KV, CKV, CIN);
    sgemm_nt<<<dim3(CQ / 128, M_Q / 128), 256>>>(sXsub, Wq, sQ, M_Q, CQ, CIN);

    // 3. BN stats (deterministic 2-stage)
    bn_partial<<<dim3(CKV / 32, 32), dim3(32, 8)>>>(sKV, M_KV, CKV, psum, psq);
    bn_finalize<<<1, CKV>>>(psum, psq, gkv, bkv, CKV, 1.f / M_KV, aKV, shKV);
    bn_partial<<<dim3(CQ / 32, 32), dim3(32, 8)>>>(sQ, M_Q, CQ, psum, psq);
    bn_finalize<<<1, CQ>>>(psum, psq, gq, bq, CQ, 1.f / M_Q, aQ, shQ);

    // 4. attention (BN affines folded in, hard_swish fused in epilogue)
    attn_kernel<<<dim3(NQ / 64, NH, BB), 64>>>(sQ, sKV, aQ, shQ, aKV, shKV, sO);

    // 5. output projection + BN
    sgemm_nt<<<dim3(COUT / 128, M_Q / 128), 256>>>(sO, Wp, sP, M_Q, COUT, DHD);
    bn_partial<<<dim3(COUT / 32, 32), dim3(32, 8)>>>(sP, M_Q, COUT, psum, psq);
    bn_finalize<<<1, COUT>>>(psum, psq, gp, bp, COUT, 1.f / M_Q, aP, shP);
    apply_affine_out<<<(M_Q * COUT / 4) / 256, 256>>>(sP, aP, shP, out);
}

// round 7
// speedup vs baseline: 1.3881x; 1.3881x over previous
#include <cuda_runtime.h>
#include <cuda_bf16.h>
#include <cstdint>
#include <math.h>

// ---------------- problem constants ----------------
#define BB 64
#define NTOK 1280      // N (keys)
#define NQ 320         // N_ (queries)
#define CIN 256
#define CKV 768        // NH_KD + DH
#define CQ 256         // NH_KD
#define DHD 512        // DH
#define COUT 512
#define NH 8
#define KD 32
#define DV 64
#define EPSBN 1e-5f
#define SCALE_ATTN 0.17677669529663687f  // 32^-0.5

#define M_KV (BB*NTOK)   // 81920
#define M_Q  (BB*NQ)     // 20480

// ---------------- device scratch (no allocations allowed) ----------------
__device__ float g_sKV[(size_t)M_KV * CKV];     // raw KV gemm output
__device__ float g_sXsub[(size_t)M_Q * CIN];    // gathered subsampled x
__device__ float g_sQ[(size_t)M_Q * CQ];        // raw Q gemm output
__device__ float g_sO[(size_t)M_Q * DHD];       // hard_swish(attention output)
__device__ float g_sP[(size_t)M_Q * COUT];      // raw out-proj gemm
__device__ float g_psum[CKV * 32];
__device__ float g_psq[CKV * 32];
__device__ float g_aKV[CKV], g_shKV[CKV];
__device__ float g_aQ[CQ],  g_shQ[CQ];
__device__ float g_aP[COUT], g_shP[COUT];

// ---------------- gather subsampled query tokens ----------------
__global__ void gather_q_kernel(const float* __restrict__ x, float* __restrict__ xs)
{
    int idx = blockIdx.x * blockDim.x + threadIdx.x;   // 20480*64
    int row = idx >> 6;
    int f   = idx & 63;
    int b = row / NQ;
    int i = row - b * NQ;
    int src;
    if (i < 256) {
        int r = i >> 4, c = i & 15;
        src = (r * 2) * 32 + c * 2;
    } else {
        int j = i - 256;
        int r = j >> 3, c = j & 7;
        src = 1024 + (r * 2) * 16 + c * 2;
    }
    const float4* xp = (const float4*)x;
    float4* op = (float4*)xs;
    op[(size_t)row * 64 + f] = xp[((size_t)b * NTOK + src) * 64 + f];
}

// ---------------- tf32 tensor-core GEMM, C = A(MxK) * B(NxK)^T ----------------
#define LDSW 36   // 32 + 4 pad: (4*gid+tg) mod 32 injective -> conflict-free frags

__device__ __forceinline__ unsigned int f2tf(float f) {
    unsigned int r;
    asm("cvt.rna.tf32.f32 %0, %1;" : "=r"(r) : "f"(f));
    return r;
}

__device__ __forceinline__ void mma8(float* c, const unsigned int* a, const unsigned int* b) {
    asm volatile(
        "mma.sync.aligned.m16n8k8.row.col.f32.tf32.tf32.f32 "
        "{%0,%1,%2,%3}, {%4,%5,%6,%7}, {%8,%9}, {%0,%1,%2,%3};"
        : "+f"(c[0]), "+f"(c[1]), "+f"(c[2]), "+f"(c[3])
        : "r"(a[0]), "r"(a[1]), "r"(a[2]), "r"(a[3]), "r"(b[0]), "r"(b[1]));
}

__device__ __forceinline__ void cp_async16(unsigned int smem_addr, const void* gptr) {
    asm volatile("cp.async.cg.shared.global [%0], [%1], 16;\n"
                 :: "r"(smem_addr), "l"(gptr));
}

__global__ __launch_bounds__(256, 2)
void gemm_tf32_nt(const float* __restrict__ A, const float* __restrict__ B,
                  float* __restrict__ C, int M, int N, int K)
{
    __shared__ float As[128 * LDSW];
    __shared__ float Bs[128 * LDSW];

    int tid = threadIdx.x;
    int bm = blockIdx.y * 128, bn = blockIdx.x * 128;
    int wid = tid >> 5, lane = tid & 31;
    int wm = (wid >> 1) << 5;    // 0,32,64,96
    int wn = (wid & 1) << 6;     // 0,64
    int gid = lane >> 2, tg = lane & 3;

    float acc[2][8][4];
#pragma unroll
    for (int im = 0; im < 2; im++)
#pragma unroll
        for (int j = 0; j < 8; j++)
#pragma unroll
            for (int r = 0; r < 4; r++) acc[im][j][r] = 0.f;

    unsigned int sA = (unsigned int)__cvta_generic_to_shared(As);
    unsigned int sB = (unsigned int)__cvta_generic_to_shared(Bs);

    int nch = K >> 5;   // K/32

    // stage chunk 0
#pragma unroll
    for (int i = 0; i < 4; i++) {
        int idx = i * 256 + tid, row = idx >> 3, c4 = idx & 7;
        unsigned int off = (unsigned int)((row * LDSW + c4 * 4) << 2);
        cp_async16(sA + off, A + (size_t)(bm + row) * K + c4 * 4);
        cp_async16(sB + off, B + (size_t)(bn + row) * K + c4 * 4);
    }
    asm volatile("cp.async.commit_group;\n");

    for (int c = 0; c < nch; c++) {
        asm volatile("cp.async.wait_group 0;\n");
        __syncthreads();

#pragma unroll
        for (int s = 0; s < 4; s++) {
            int kk = s * 8;
            unsigned int af[2][4], bf[8][2];
#pragma unroll
            for (int im = 0; im < 2; im++) {
                const float* p = As + (wm + im * 16 + gid) * LDSW + kk + tg;
                af[im][0] = f2tf(p[0]);
                af[im][1] = f2tf(p[8 * LDSW]);
                af[im][2] = f2tf(p[4]);
                af[im][3] = f2tf(p[8 * LDSW + 4]);
            }
#pragma unroll
            for (int j = 0; j < 8; j++) {
                const float* p = Bs + (wn + j * 8 + gid) * LDSW + kk + tg;
                bf[j][0] = f2tf(p[0]);
                bf[j][1] = f2tf(p[4]);
            }
#pragma unroll
            for (int im = 0; im < 2; im++)
#pragma unroll
                for (int j = 0; j < 8; j++)
                    mma8(acc[im][j], af[im], bf[j]);
        }

        __syncthreads();
        if (c + 1 < nch) {
            int k0 = (c + 1) << 5;
#pragma unroll
            for (int i = 0; i < 4; i++) {
                int idx = i * 256 + tid, row = idx >> 3, c4 = idx & 7;
                unsigned int off = (unsigned int)((row * LDSW + c4 * 4) << 2);
                cp_async16(sA + off, A + (size_t)(bm + row) * K + k0 + c4 * 4);
                cp_async16(sB + off, B + (size_t)(bn + row) * K + k0 + c4 * 4);
            }
            asm volatile("cp.async.commit_group;\n");
        }
    }

    // epilogue
#pragma unroll
    for (int im = 0; im < 2; im++) {
        int r0 = bm + wm + im * 16 + gid;
#pragma unroll
        for (int j = 0; j < 8; j++) {
            int c0 = bn + wn + j * 8 + tg * 2;
            *(float2*)&C[(size_t)r0 * N + c0]       = make_float2(acc[im][j][0], acc[im][j][1]);
            *(float2*)&C[(size_t)(r0 + 8) * N + c0] = make_float2(acc[im][j][2], acc[im][j][3]);
        }
    }
}

// ---------------- BN stats: stage 1 (deterministic partials) ----------------
__global__ void bn_partial(const float* __restrict__ Y, int M, int C,
                           float* __restrict__ psum, float* __restrict__ psq)
{
    int col = blockIdx.x * 32 + threadIdx.x;
    int chunk = M / 32;
    int r0 = blockIdx.y * chunk;
    float s = 0.f, s2 = 0.f;
    for (int r = r0 + threadIdx.y; r < r0 + chunk; r += 8) {
        float v = Y[(size_t)r * C + col];
        s += v; s2 += v * v;
    }
    __shared__ float ssum[8][32];
    __shared__ float ssq[8][32];
    ssum[threadIdx.y][threadIdx.x] = s;
    ssq[threadIdx.y][threadIdx.x] = s2;
    __syncthreads();
    if (threadIdx.y == 0) {
        float ts = 0.f, ts2 = 0.f;
#pragma unroll
        for (int y = 0; y < 8; y++) { ts += ssum[y][threadIdx.x]; ts2 += ssq[y][threadIdx.x]; }
        psum[blockIdx.y * C + col] = ts;
        psq[blockIdx.y * C + col]  = ts2;
    }
}

__global__ void bn_finalize(const float* __restrict__ psum, const float* __restrict__ psq,
                            const float* __restrict__ g, const float* __restrict__ bta,
                            int C, float invM, float* __restrict__ a, float* __restrict__ sh)
{
    int c = threadIdx.x;
    if (c >= C) return;
    float s = 0.f, s2 = 0.f;
    for (int r = 0; r < 32; r++) { s += psum[r * C + c]; s2 += psq[r * C + c]; }
    float mean = s * invM;
    float var = s2 * invM - mean * mean;
    float aa = g[c] * rsqrtf(var + EPSBN);
    a[c] = aa;
    sh[c] = bta[c] - mean * aa;
}

// ---------------- attention: flash-style, 1 thread = 1 query ----------------
__global__ __launch_bounds__(64)
void attn_kernel(const float* __restrict__ Q, const float* __restrict__ KV,
                 const float* __restrict__ aQ, const float* __restrict__ shQ,
                 const float* __restrict__ aKV, const float* __restrict__ shKV,
                 float* __restrict__ O)
{
    int t = threadIdx.x;
    int qt = blockIdx.x, h = blockIdx.y, b = blockIdx.z;
    int nq = qt * 64 + t;

    __shared__ float4 ks[64][8];    // 64 keys x 32 k-dims
    __shared__ float4 vs[64][16];   // 64 keys x 64 v-dims
    __shared__ float aC[96], sC[96];

    for (int i = t; i < 96; i += 64) {
        aC[i] = aKV[h * 96 + i];
        sC[i] = shKV[h * 96 + i];
    }

    float q[32];
    {
        const float* qrow = Q + ((size_t)(b * NQ + nq)) * CQ + h * KD;
#pragma unroll
        for (int j = 0; j < 32; j++)
            q[j] = (qrow[j] * aQ[h * KD + j] + shQ[h * KD + j]) * SCALE_ATTN;
    }

    float o[64];
#pragma unroll
    for (int d = 0; d < 64; d++) o[d] = 0.f;
    float l = 0.f;

    for (int kt = 0; kt < NTOK / 64; kt++) {
        __syncthreads();
        for (int idx = t; idx < 64 * 24; idx += 64) {
            int row = idx / 24, f = idx % 24;
            const float4* rp = (const float4*)(KV + ((size_t)(b * NTOK + kt * 64 + row)) * CKV + h * 96);
            float4 v = rp[f];
            int c = f * 4;
            v.x = v.x * aC[c + 0] + sC[c + 0];
            v.y = v.y * aC[c + 1] + sC[c + 1];
            v.z = v.z * aC[c + 2] + sC[c + 2];
            v.w = v.w * aC[c + 3] + sC[c + 3];
            if (f < 8) ks[row][f] = v; else vs[row][f - 8] = v;
        }
        __syncthreads();

#pragma unroll 2
        for (int kk = 0; kk < 64; kk++) {
            float s = 0.f;
#pragma unroll
            for (int f = 0; f < 8; f++) {
                float4 k4 = ks[kk][f];
                s += q[f * 4 + 0] * k4.x + q[f * 4 + 1] * k4.y
                   + q[f * 4 + 2] * k4.z + q[f * 4 + 3] * k4.w;
            }
            float p = __expf(s);   // BN'd scores are O(1): safe without max-subtract
            l += p;
#pragma unroll
            for (int f = 0; f < 16; f++) {
                float4 v4 = vs[kk][f];
                o[f * 4 + 0] += p * v4.x;
                o[f * 4 + 1] += p * v4.y;
                o[f * 4 + 2] += p * v4.z;
                o[f * 4 + 3] += p * v4.w;
            }
        }
    }

    float inv = 1.f / l;
    float* orow = O + ((size_t)(b * NQ + nq)) * DHD + h * DV;
#pragma unroll
    for (int f = 0; f < 16; f++) {
        float4 r;
        float v0 = o[f * 4 + 0] * inv, v1 = o[f * 4 + 1] * inv;
        float v2 = o[f * 4 + 2] * inv, v3 = o[f * 4 + 3] * inv;
        r.x = v0 * fminf(fmaxf(v0 + 3.f, 0.f), 6.f) * (1.f / 6.f);
        r.y = v1 * fminf(fmaxf(v1 + 3.f, 0.f), 6.f) * (1.f / 6.f);
        r.z = v2 * fminf(fmaxf(v2 + 3.f, 0.f), 6.f) * (1.f / 6.f);
        r.w = v3 * fminf(fmaxf(v3 + 3.f, 0.f), 6.f) * (1.f / 6.f);
        ((float4*)orow)[f] = r;
    }
}

// ---------------- final BN-affine into d_out ----------------
__global__ void apply_affine_out(const float* __restrict__ Y,
                                 const float* __restrict__ a, const float* __restrict__ sh,
                                 float* __restrict__ out)
{
    int idx = blockIdx.x * blockDim.x + threadIdx.x;
    int c4 = idx & 127;
    float4 y = ((const float4*)Y)[idx];
    float4 aa = ((const float4*)a)[c4];
    float4 ss = ((const float4*)sh)[c4];
    float4 r;
    r.x = y.x * aa.x + ss.x;
    r.y = y.y * aa.y + ss.y;
    r.z = y.z * aa.z + ss.z;
    r.w = y.w * aa.w + ss.w;
    ((float4*)out)[idx] = r;
}

// ---------------- launch ----------------
extern "C" void kernel_launch(void* const* d_in, const int* in_sizes, int n_in,
                              void* d_out, int out_size)
{
    const float* x   = (const float*)d_in[0];
    const float* Wkv = (const float*)d_in[1];
    const float* gkv = (const float*)d_in[2];
    const float* bkv = (const float*)d_in[3];
    const float* Wq  = (const float*)d_in[4];
    const float* gq  = (const float*)d_in[5];
    const float* bq  = (const float*)d_in[6];
    const float* Wp  = (const float*)d_in[7];
    const float* gp  = (const float*)d_in[8];
    const float* bp  = (const float*)d_in[9];
    float* out = (float*)d_out;

    float *sKV, *sXsub, *sQ, *sO, *sP, *psum, *psq;
    float *aKV, *shKV, *aQ, *shQ, *aP, *shP;
    cudaGetSymbolAddress((void**)&sKV,   g_sKV);
    cudaGetSymbolAddress((void**)&sXsub, g_sXsub);
    cudaGetSymbolAddress((void**)&sQ,    g_sQ);
    cudaGetSymbolAddress((void**)&sO,    g_sO);
    cudaGetSymbolAddress((void**)&sP,    g_sP);
    cudaGetSymbolAddress((void**)&psum,  g_psum);
    cudaGetSymbolAddress((void**)&psq,   g_psq);
    cudaGetSymbolAddress((void**)&aKV,   g_aKV);
    cudaGetSymbolAddress((void**)&shKV,  g_shKV);
    cudaGetSymbolAddress((void**)&aQ,    g_aQ);
    cudaGetSymbolAddress((void**)&shQ,   g_shQ);
    cudaGetSymbolAddress((void**)&aP,    g_aP);
    cudaGetSymbolAddress((void**)&shP,   g_shP);

    // 1. gather subsampled query tokens
    gather_q_kernel<<<(M_Q * (CIN / 4)) / 256, 256>>>(x, sXsub);

    // 2. KV and Q projections (tf32 tensor cores)
    gemm_tf32_nt<<<dim3(CKV / 128, M_KV / 128), 256>>>(x, Wkv, sKV, M_KV, CKV, CIN);
    gemm_tf32_nt<<<dim3(CQ / 128, M_Q / 128), 256>>>(sXsub, Wq, sQ, M_Q, CQ, CIN);

    // 3. BN stats (deterministic 2-stage)
    bn_partial<<<dim3(CKV / 32, 32), dim3(32, 8)>>>(sKV, M_KV, CKV, psum, psq);
    bn_finalize<<<1, CKV>>>(psum, psq, gkv, bkv, CKV, 1.f / M_KV, aKV, shKV);
    bn_partial<<<dim3(CQ / 32, 32), dim3(32, 8)>>>(sQ, M_Q, CQ, psum, psq);
    bn_finalize<<<1, CQ>>>(psum, psq, gq, bq, CQ, 1.f / M_Q, aQ, shQ);

    // 4. attention (BN affines folded in, hard_swish fused in epilogue)
    attn_kernel<<<dim3(NQ / 64, NH, BB), 64>>>(sQ, sKV, aQ, shQ, aKV, shKV, sO);

    // 5. output projection + BN
    gemm_tf32_nt<<<dim3(COUT / 128, M_Q / 128), 256>>>(sO, Wp, sP, M_Q, COUT, DHD);
    bn_partial<<<dim3(COUT / 32, 32), dim3(32, 8)>>>(sP, M_Q, COUT, psum, psq);
    bn_finalize<<<1, COUT>>>(psum, psq, gp, bp, COUT, 1.f / M_Q, aP, shP);
    apply_affine_out<<<(M_Q * COUT / 4) / 256, 256>>>(sP, aP, shP, out);
}

// round 9
// speedup vs baseline: 2.6349x; 1.8982x over previous
#include <cuda_runtime.h>
#include <cuda_bf16.h>
#include <cstdint>
#include <math.h>

// ---------------- problem constants ----------------
#define BB 64
#define NTOK 1280      // N (keys)
#define NQ 320         // N_ (queries)
#define CIN 256
#define CKV 768        // NH_KD + DH
#define CQ 256         // NH_KD
#define DHD 512        // DH
#define COUT 512
#define NH 8
#define KD 32
#define DV 64
#define EPSBN 1e-5f
#define SCALE_ATTN 0.17677669529663687f  // 32^-0.5
#define LOG2E 1.4426950408889634f

#define M_KV (BB*NTOK)   // 81920
#define M_Q  (BB*NQ)     // 20480

// ---------------- device scratch (no allocations allowed) ----------------
__device__ float g_sKV[(size_t)M_KV * CKV];     // raw KV gemm output
__device__ float g_sXsub[(size_t)M_Q * CIN];    // gathered subsampled x
__device__ float g_sQ[(size_t)M_Q * CQ];        // raw Q gemm output
__device__ float g_sO[(size_t)M_Q * DHD];       // hard_swish(attention output)
__device__ float g_sP[(size_t)M_Q * COUT];      // raw out-proj gemm
__device__ float g_Qt[(size_t)BB * NH * NQ * KD];     // prepped Q  [b,h,320,32]
__device__ float g_Kt[(size_t)BB * NH * NTOK * KD];   // prepped K  [b,h,1280,32]
__device__ float g_Vt[(size_t)BB * NH * NTOK * DV];   // prepped V  [b,h,1280,64]
__device__ float g_psum[CKV * 32];
__device__ float g_psq[CKV * 32];
__device__ float g_aKV[CKV], g_shKV[CKV];
__device__ float g_aQ[CQ],  g_shQ[CQ];
__device__ float g_aP[COUT], g_shP[COUT];

// ---------------- common PTX helpers ----------------
__device__ __forceinline__ unsigned int f2tf(float f) {
    unsigned int r;
    asm("cvt.rna.tf32.f32 %0, %1;" : "=r"(r) : "f"(f));
    return r;
}

__device__ __forceinline__ float ex2f(float x) {
    float r;
    asm("ex2.approx.f32 %0, %1;" : "=f"(r) : "f"(x));
    return r;
}

__device__ __forceinline__ void mma8(float* c, const unsigned int* a, const unsigned int* b) {
    asm volatile(
        "mma.sync.aligned.m16n8k8.row.col.f32.tf32.tf32.f32 "
        "{%0,%1,%2,%3}, {%4,%5,%6,%7}, {%8,%9}, {%0,%1,%2,%3};"
        : "+f"(c[0]), "+f"(c[1]), "+f"(c[2]), "+f"(c[3])
        : "r"(a[0]), "r"(a[1]), "r"(a[2]), "r"(a[3]), "r"(b[0]), "r"(b[1]));
}

__device__ __forceinline__ void cp_async16(unsigned int smem_addr, const void* gptr) {
    asm volatile("cp.async.cg.shared.global [%0], [%1], 16;\n"
                 :: "r"(smem_addr), "l"(gptr));
}

// ---------------- gather subsampled query tokens ----------------
__global__ void gather_q_kernel(const float* __restrict__ x, float* __restrict__ xs)
{
    int idx = blockIdx.x * blockDim.x + threadIdx.x;
    int row = idx >> 6;
    int f   = idx & 63;
    int b = row / NQ;
    int i = row - b * NQ;
    int src;
    if (i < 256) {
        int r = i >> 4, c = i & 15;
        src = (r * 2) * 32 + c * 2;
    } else {
        int j = i - 256;
        int r = j >> 3, c = j & 7;
        src = 1024 + (r * 2) * 16 + c * 2;
    }
    const float4* xp = (const float4*)x;
    float4* op = (float4*)xs;
    op[(size_t)row * 64 + f] = xp[((size_t)b * NTOK + src) * 64 + f];
}

// ---------------- tf32 tensor-core GEMM, C = A(MxK) * B(NxK)^T ----------------
#define LDSW 36   // 32 + 4 pad

__global__ __launch_bounds__(256, 2)
void gemm_tf32_nt(const float* __restrict__ A, const float* __restrict__ B,
                  float* __restrict__ C, int M, int N, int K)
{
    __shared__ float As[128 * LDSW];
    __shared__ float Bs[128 * LDSW];

    int tid = threadIdx.x;
    int bm = blockIdx.y * 128, bn = blockIdx.x * 128;
    int wid = tid >> 5, lane = tid & 31;
    int wm = (wid >> 1) << 5;
    int wn = (wid & 1) << 6;
    int gid = lane >> 2, tg = lane & 3;

    float acc[2][8][4];
#pragma unroll
    for (int im = 0; im < 2; im++)
#pragma unroll
        for (int j = 0; j < 8; j++)
#pragma unroll
            for (int r = 0; r < 4; r++) acc[im][j][r] = 0.f;

    unsigned int sA = (unsigned int)__cvta_generic_to_shared(As);
    unsigned int sB = (unsigned int)__cvta_generic_to_shared(Bs);

    int nch = K >> 5;

#pragma unroll
    for (int i = 0; i < 4; i++) {
        int idx = i * 256 + tid, row = idx >> 3, c4 = idx & 7;
        unsigned int off = (unsigned int)((row * LDSW + c4 * 4) << 2);
        cp_async16(sA + off, A + (size_t)(bm + row) * K + c4 * 4);
        cp_async16(sB + off, B + (size_t)(bn + row) * K + c4 * 4);
    }
    asm volatile("cp.async.commit_group;\n");

    for (int c = 0; c < nch; c++) {
        asm volatile("cp.async.wait_group 0;\n");
        __syncthreads();

#pragma unroll
        for (int s = 0; s < 4; s++) {
            int kk = s * 8;
            unsigned int af[2][4], bf[8][2];
#pragma unroll
            for (int im = 0; im < 2; im++) {
                const float* p = As + (wm + im * 16 + gid) * LDSW + kk + tg;
                af[im][0] = f2tf(p[0]);
                af[im][1] = f2tf(p[8 * LDSW]);
                af[im][2] = f2tf(p[4]);
                af[im][3] = f2tf(p[8 * LDSW + 4]);
            }
#pragma unroll
            for (int j = 0; j < 8; j++) {
                const float* p = Bs + (wn + j * 8 + gid) * LDSW + kk + tg;
                bf[j][0] = f2tf(p[0]);
                bf[j][1] = f2tf(p[4]);
            }
#pragma unroll
            for (int im = 0; im < 2; im++)
#pragma unroll
                for (int j = 0; j < 8; j++)
                    mma8(acc[im][j], af[im], bf[j]);
        }

        __syncthreads();
        if (c + 1 < nch) {
            int k0 = (c + 1) << 5;
#pragma unroll
            for (int i = 0; i < 4; i++) {
                int idx = i * 256 + tid, row = idx >> 3, c4 = idx & 7;
                unsigned int off = (unsigned int)((row * LDSW + c4 * 4) << 2);
                cp_async16(sA + off, A + (size_t)(bm + row) * K + k0 + c4 * 4);
                cp_async16(sB + off, B + (size_t)(bn + row) * K + k0 + c4 * 4);
            }
            asm volatile("cp.async.commit_group;\n");
        }
    }

#pragma unroll
    for (int im = 0; im < 2; im++) {
        int r0 = bm + wm + im * 16 + gid;
#pragma unroll
        for (int j = 0; j < 8; j++) {
            int c0 = bn + wn + j * 8 + tg * 2;
            *(float2*)&C[(size_t)r0 * N + c0]       = make_float2(acc[im][j][0], acc[im][j][1]);
            *(float2*)&C[(size_t)(r0 + 8) * N + c0] = make_float2(acc[im][j][2], acc[im][j][3]);
        }
    }
}

// ---------------- BN stats ----------------
__global__ void bn_partial(const float* __restrict__ Y, int M, int C,
                           float* __restrict__ psum, float* __restrict__ psq)
{
    int col = blockIdx.x * 32 + threadIdx.x;
    int chunk = M / 32;
    int r0 = blockIdx.y * chunk;
    float s = 0.f, s2 = 0.f;
    for (int r = r0 + threadIdx.y; r < r0 + chunk; r += 8) {
        float v = Y[(size_t)r * C + col];
        s += v; s2 += v * v;
    }
    __shared__ float ssum[8][32];
    __shared__ float ssq[8][32];
    ssum[threadIdx.y][threadIdx.x] = s;
    ssq[threadIdx.y][threadIdx.x] = s2;
    __syncthreads();
    if (threadIdx.y == 0) {
        float ts = 0.f, ts2 = 0.f;
#pragma unroll
        for (int y = 0; y < 8; y++) { ts += ssum[y][threadIdx.x]; ts2 += ssq[y][threadIdx.x]; }
        psum[blockIdx.y * C + col] = ts;
        psq[blockIdx.y * C + col]  = ts2;
    }
}

__global__ void bn_finalize(const float* __restrict__ psum, const float* __restrict__ psq,
                            const float* __restrict__ g, const float* __restrict__ bta,
                            int C, float invM, float* __restrict__ a, float* __restrict__ sh)
{
    int c = threadIdx.x;
    if (c >= C) return;
    float s = 0.f, s2 = 0.f;
    for (int r = 0; r < 32; r++) { s += psum[r * C + c]; s2 += psq[r * C + c]; }
    float mean = s * invM;
    float var = s2 * invM - mean * mean;
    float aa = g[c] * rsqrtf(var + EPSBN);
    a[c] = aa;
    sh[c] = bta[c] - mean * aa;
}

// ---------------- prep: BN-affined head-major K/V and pre-scaled Q ----------------
// over M_KV * 192 float4s
__global__ void prep_kv(const float* __restrict__ KV,
                        const float* __restrict__ a, const float* __restrict__ sh,
                        float* __restrict__ Kt, float* __restrict__ Vt)
{
    size_t idx = (size_t)blockIdx.x * 256 + threadIdx.x;
    int row = (int)(idx / 192);           // b*1280 + n
    int c4  = (int)(idx % 192);
    int b = row / NTOK, n = row - b * NTOK;
    int h = c4 / 24, j4 = c4 % 24;
    int c = c4 * 4;
    float4 v = ((const float4*)KV)[(size_t)row * 192 + c4];
    v.x = v.x * a[c + 0] + sh[c + 0];
    v.y = v.y * a[c + 1] + sh[c + 1];
    v.z = v.z * a[c + 2] + sh[c + 2];
    v.w = v.w * a[c + 3] + sh[c + 3];
    if (j4 < 8)
        ((float4*)Kt)[((size_t)(b * NH + h) * NTOK + n) * 8 + j4] = v;
    else
        ((float4*)Vt)[((size_t)(b * NH + h) * NTOK + n) * 16 + (j4 - 8)] = v;
}

// over M_Q * 64 float4s
__global__ void prep_q(const float* __restrict__ Q,
                       const float* __restrict__ a, const float* __restrict__ sh,
                       float* __restrict__ Qt)
{
    size_t idx = (size_t)blockIdx.x * 256 + threadIdx.x;
    int row = (int)(idx / 64);            // b*320 + q
    int c4  = (int)(idx % 64);
    int b = row / NQ, q = row - b * NQ;
    int h = c4 / 8, j4 = c4 % 8;
    int c = c4 * 4;
    const float SC = SCALE_ATTN * LOG2E;
    float4 v = ((const float4*)Q)[(size_t)row * 64 + c4];
    v.x = (v.x * a[c + 0] + sh[c + 0]) * SC;
    v.y = (v.y * a[c + 1] + sh[c + 1]) * SC;
    v.z = (v.z * a[c + 2] + sh[c + 2]) * SC;
    v.w = (v.w * a[c + 3] + sh[c + 3]) * SC;
    ((float4*)Qt)[((size_t)(b * NH + h) * NQ + q) * 8 + j4] = v;
}

// ---------------- tensor-core flash attention ----------------
// smem layout (floats): buf0 K[64*36] V[64*72] = 6912 | buf1 = 6912 | P: 4 warps * 16*68
#define SM_KSTR 36
#define SM_VSTR 72
#define SM_PSTR 68
#define SM_BUF  6912
#define SM_POFF 13824
#define SM_TOTALF (SM_POFF + 4 * 16 * SM_PSTR)   // 18176 floats = 72704 B

__device__ __forceinline__ void stage_tile(unsigned int smem_bytes,
                                           const float* __restrict__ Kg,
                                           const float* __restrict__ Vg,
                                           int kt, int tid)
{
    const float4* Ks = (const float4*)(Kg + (size_t)kt * 64 * KD);
    const float4* Vs = (const float4*)(Vg + (size_t)kt * 64 * DV);
#pragma unroll
    for (int i = 0; i < 4; i++) {
        int idx = i * 128 + tid; int r = idx >> 3, f = idx & 7;
        cp_async16(smem_bytes + (unsigned int)((r * SM_KSTR + f * 4) << 2), Ks + r * 8 + f);
    }
#pragma unroll
    for (int i = 0; i < 8; i++) {
        int idx = i * 128 + tid; int r = idx >> 4, f = idx & 15;
        cp_async16(smem_bytes + (unsigned int)((2304 + r * SM_VSTR + f * 4) << 2), Vs + r * 16 + f);
    }
}

__device__ __forceinline__ float hswish(float x) {
    return x * fminf(fmaxf(x + 3.f, 0.f), 6.f) * (1.f / 6.f);
}

__global__ __launch_bounds__(128)
void attn_tc(const float* __restrict__ Qt, const float* __restrict__ Kt,
             const float* __restrict__ Vt, float* __restrict__ O)
{
    extern __shared__ float smf[];
    int tid  = threadIdx.x;
    int warp = tid >> 5, lane = tid & 31;
    int gid = lane >> 2, tg = lane & 3;
    int qt = blockIdx.x, h = blockIdx.y, b = blockIdx.z;
    int bh = b * NH + h;

    const float* Kg = Kt + (size_t)bh * NTOK * KD;
    const float* Vg = Vt + (size_t)bh * NTOK * DV;
    unsigned int smb = (unsigned int)__cvta_generic_to_shared(smf);
    float* Pw = smf + SM_POFF + warp * (16 * SM_PSTR);

    // Q fragments (persist in registers; pre-scaled by SCALE*log2e)
    int q0 = qt * 64 + warp * 16;
    const float* Qg = Qt + ((size_t)bh * NQ + q0) * KD;
    unsigned int qa[4][4];
#pragma unroll
    for (int kc = 0; kc < 4; kc++) {
        qa[kc][0] = f2tf(__ldg(Qg + gid * KD + kc * 8 + tg));
        qa[kc][1] = f2tf(__ldg(Qg + (gid + 8) * KD + kc * 8 + tg));
        qa[kc][2] = f2tf(__ldg(Qg + gid * KD + kc * 8 + tg + 4));
        qa[kc][3] = f2tf(__ldg(Qg + (gid + 8) * KD + kc * 8 + tg + 4));
    }

    float acc[8][4];
#pragma unroll
    for (int nt = 0; nt < 8; nt++)
#pragma unroll
        for (int r = 0; r < 4; r++) acc[nt][r] = 0.f;
    float l0 = 0.f, l1 = 0.f;

    stage_tile(smb, Kg, Vg, 0, tid);
    asm volatile("cp.async.commit_group;\n");

    const int NKT = NTOK / 64;   // 20
    for (int kt = 0; kt < NKT; kt++) {
        if (kt + 1 < NKT) {
            stage_tile(smb + ((kt + 1) & 1) * SM_BUF * 4, Kg, Vg, kt + 1, tid);
            asm volatile("cp.async.commit_group;\n");
            asm volatile("cp.async.wait_group 1;\n");
        } else {
            asm volatile("cp.async.wait_group 0;\n");
        }
        __syncthreads();

        const float* Ksm = smf + (kt & 1) * SM_BUF;
        const float* Vsm = Ksm + 2304;

        // S = Q K^T (tf32), then p = 2^S, row-sum, stash P in warp-private smem
#pragma unroll
        for (int nt = 0; nt < 8; nt++) {
            float c[4] = {0.f, 0.f, 0.f, 0.f};
#pragma unroll
            for (int kc = 0; kc < 4; kc++) {
                unsigned int bb[2];
                const float* kp = Ksm + (nt * 8 + gid) * SM_KSTR + kc * 8 + tg;
                bb[0] = f2tf(kp[0]);
                bb[1] = f2tf(kp[4]);
                mma8(c, qa[kc], bb);
            }
            float p0 = ex2f(c[0]), p1 = ex2f(c[1]);
            float p2 = ex2f(c[2]), p3 = ex2f(c[3]);
            l0 += p0 + p1;
            l1 += p2 + p3;
            *(float2*)&Pw[gid * SM_PSTR + nt * 8 + 2 * tg]       = make_float2(p0, p1);
            *(float2*)&Pw[(gid + 8) * SM_PSTR + nt * 8 + 2 * tg] = make_float2(p2, p3);
        }
        __syncwarp();

        // O += P V (tf32)
#pragma unroll
        for (int kc = 0; kc < 8; kc++) {
            unsigned int pa[4];
            pa[0] = f2tf(Pw[gid * SM_PSTR + kc * 8 + tg]);
            pa[1] = f2tf(Pw[(gid + 8) * SM_PSTR + kc * 8 + tg]);
            pa[2] = f2tf(Pw[gid * SM_PSTR + kc * 8 + tg + 4]);
            pa[3] = f2tf(Pw[(gid + 8) * SM_PSTR + kc * 8 + tg + 4]);
#pragma unroll
            for (int nt = 0; nt < 8; nt++) {
                unsigned int vb[2];
                const float* vp = Vsm + (kc * 8 + tg) * SM_VSTR + nt * 8 + gid;
                vb[0] = f2tf(vp[0]);
                vb[1] = f2tf(vp[4 * SM_VSTR]);
                mma8(acc[nt], pa, vb);
            }
        }
        __syncthreads();   // protect K/V buffer before next stage overwrites
    }

    // full row-sums: reduce over the quad (tg lanes share gid)
    l0 += __shfl_xor_sync(0xffffffffu, l0, 1);
    l0 += __shfl_xor_sync(0xffffffffu, l0, 2);
    l1 += __shfl_xor_sync(0xffffffffu, l1, 1);
    l1 += __shfl_xor_sync(0xffffffffu, l1, 2);
    float inv0 = 1.f / l0, inv1 = 1.f / l1;

    // epilogue: normalize, hard-swish, store to sO[b*320+q][h*64+d]
    float* Ob = O + ((size_t)(b * NQ + q0)) * DHD + h * DV;
#pragma unroll
    for (int nt = 0; nt < 8; nt++) {
        int c0 = nt * 8 + 2 * tg;
        float v0 = acc[nt][0] * inv0, v1 = acc[nt][1] * inv0;
        float v2 = acc[nt][2] * inv1, v3 = acc[nt][3] * inv1;
        *(float2*)&Ob[(size_t)gid * DHD + c0]       = make_float2(hswish(v0), hswish(v1));
        *(float2*)&Ob[(size_t)(gid + 8) * DHD + c0] = make_float2(hswish(v2), hswish(v3));
    }
}

// ---------------- final BN-affine into d_out ----------------
__global__ void apply_affine_out(const float* __restrict__ Y,
                                 const float* __restrict__ a, const float* __restrict__ sh,
                                 float* __restrict__ out)
{
    int idx = blockIdx.x * blockDim.x + threadIdx.x;
    int c4 = idx & 127;
    float4 y = ((const float4*)Y)[idx];
    float4 aa = ((const float4*)a)[c4];
    float4 ss = ((const float4*)sh)[c4];
    float4 r;
    r.x = y.x * aa.x + ss.x;
    r.y = y.y * aa.y + ss.y;
    r.z = y.z * aa.z + ss.z;
    r.w = y.w * aa.w + ss.w;
    ((float4*)out)[idx] = r;
}

// ---------------- launch ----------------
extern "C" void kernel_launch(void* const* d_in, const int* in_sizes, int n_in,
                              void* d_out, int out_size)
{
    const float* x   = (const float*)d_in[0];
    const float* Wkv = (const float*)d_in[1];
    const float* gkv = (const float*)d_in[2];
    const float* bkv = (const float*)d_in[3];
    const float* Wq  = (const float*)d_in[4];
    const float* gq  = (const float*)d_in[5];
    const float* bq  = (const float*)d_in[6];
    const float* Wp  = (const float*)d_in[7];
    const float* gp  = (const float*)d_in[8];
    const float* bp  = (const float*)d_in[9];
    float* out = (float*)d_out;

    float *sKV, *sXsub, *sQ, *sO, *sP, *psum, *psq;
    float *aKV, *shKV, *aQ, *shQ, *aP, *shP, *Qt, *Kt, *Vt;
    cudaGetSymbolAddress((void**)&sKV,   g_sKV);
    cudaGetSymbolAddress((void**)&sXsub, g_sXsub);
    cudaGetSymbolAddress((void**)&sQ,    g_sQ);
    cudaGetSymbolAddress((void**)&sO,    g_sO);
    cudaGetSymbolAddress((void**)&sP,    g_sP);
    cudaGetSymbolAddress((void**)&psum,  g_psum);
    cudaGetSymbolAddress((void**)&psq,   g_psq);
    cudaGetSymbolAddress((void**)&aKV,   g_aKV);
    cudaGetSymbolAddress((void**)&shKV,  g_shKV);
    cudaGetSymbolAddress((void**)&aQ,    g_aQ);
    cudaGetSymbolAddress((void**)&shQ,   g_shQ);
    cudaGetSymbolAddress((void**)&aP,    g_aP);
    cudaGetSymbolAddress((void**)&shP,   g_shP);
    cudaGetSymbolAddress((void**)&Qt,    g_Qt);
    cudaGetSymbolAddress((void**)&Kt,    g_Kt);
    cudaGetSymbolAddress((void**)&Vt,    g_Vt);

    static bool attr_set = false;
    if (!attr_set) {
        cudaFuncSetAttribute(attn_tc, cudaFuncAttributeMaxDynamicSharedMemorySize,
                             SM_TOTALF * 4);
        attr_set = true;
    }

    // 1. gather subsampled query tokens
    gather_q_kernel<<<(M_Q * (CIN / 4)) / 256, 256>>>(x, sXsub);

    // 2. KV and Q projections (tf32 tensor cores)
    gemm_tf32_nt<<<dim3(CKV / 128, M_KV / 128), 256>>>(x, Wkv, sKV, M_KV, CKV, CIN);
    gemm_tf32_nt<<<dim3(CQ / 128, M_Q / 128), 256>>>(sXsub, Wq, sQ, M_Q, CQ, CIN);

    // 3. BN stats (deterministic 2-stage)
    bn_partial<<<dim3(CKV / 32, 32), dim3(32, 8)>>>(sKV, M_KV, CKV, psum, psq);
    bn_finalize<<<1, CKV>>>(psum, psq, gkv, bkv, CKV, 1.f / M_KV, aKV, shKV);
    bn_partial<<<dim3(CQ / 32, 32), dim3(32, 8)>>>(sQ, M_Q, CQ, psum, psq);
    bn_finalize<<<1, CQ>>>(psum, psq, gq, bq, CQ, 1.f / M_Q, aQ, shQ);

    // 4. prep head-major BN-affined K/V and pre-scaled Q
    prep_kv<<<(size_t)M_KV * 192 / 256, 256>>>(sKV, aKV, shKV, Kt, Vt);
    prep_q<<<(size_t)M_Q * 64 / 256, 256>>>(sQ, aQ, shQ, Qt);

    // 5. tensor-core flash attention (hard_swish fused)
    attn_tc<<<dim3(NQ / 64, NH, BB), 128, SM_TOTALF * 4>>>(Qt, Kt, Vt, sO);

    // 6. output projection + BN
    gemm_tf32_nt<<<dim3(COUT / 128, M_Q / 128), 256>>>(sO, Wp, sP, M_Q, COUT, DHD);
    bn_partial<<<dim3(COUT / 32, 32), dim3(32, 8)>>>(sP, M_Q, COUT, psum, psq);
    bn_finalize<<<1, COUT>>>(psum, psq, gp, bp, COUT, 1.f / M_Q, aP, shP);
    apply_affine_out<<<(M_Q * COUT / 4) / 256, 256>>>(sP, aP, shP, out);
}

// round 13
// speedup vs baseline: 3.0357x; 1.1521x over previous
#include <cuda_runtime.h>
#include <cuda_bf16.h>
#include <cstdint>
#include <math.h>

// ---------------- problem constants ----------------
#define BB 64
#define NTOK 1280      // N (keys)
#define NQ 320         // N_ (queries)
#define CIN 256
#define CKV 768        // NH_KD + DH
#define CQ 256         // NH_KD
#define DHD 512        // DH
#define COUT 512
#define NH 8
#define KD 32
#define DV 64
#define EPSBN 1e-5f
#define SCALE_ATTN 0.17677669529663687f  // 32^-0.5
#define LOG2E 1.4426950408889634f

#define M_KV (BB*NTOK)   // 81920
#define M_Q  (BB*NQ)     // 20480

// ---------------- device scratch (no allocations allowed) ----------------
__device__ float g_sXsub[(size_t)M_Q * CIN];    // gathered subsampled x
__device__ float g_sO[(size_t)M_Q * DHD];       // hard_swish(attention output)
__device__ float g_sP[(size_t)M_Q * COUT];      // raw out-proj gemm
__device__ float g_Qt[(size_t)BB * NH * NQ * KD];     // raw Q, head-major [b,h,320,32]
__device__ float g_Kt[(size_t)BB * NH * NTOK * KD];   // raw K, head-major [b,h,1280,32]
__device__ float g_Vt[(size_t)BB * NH * NTOK * DV];   // raw V, head-major [b,h,1280,64]
__device__ float g_psumKV[640 * CKV], g_psqKV[640 * CKV];
__device__ float g_psumQ[160 * CQ],   g_psqQ[160 * CQ];
__device__ float g_psumP[160 * COUT], g_psqP[160 * COUT];
__device__ float g_aKV[CKV], g_shKV[CKV];
__device__ float g_aQ[CQ],  g_shQ[CQ];
__device__ float g_aP[COUT], g_shP[COUT];

// ---------------- common PTX helpers ----------------
__device__ __forceinline__ unsigned int f2tf(float f) {
    unsigned int r;
    asm("cvt.rna.tf32.f32 %0, %1;" : "=r"(r) : "f"(f));
    return r;
}

__device__ __forceinline__ float ex2f(float x) {
    float r;
    asm("ex2.approx.f32 %0, %1;" : "=f"(r) : "f"(x));
    return r;
}

__device__ __forceinline__ void mma8(float* c, const unsigned int* a, const unsigned int* b) {
    asm volatile(
        "mma.sync.aligned.m16n8k8.row.col.f32.tf32.tf32.f32 "
        "{%0,%1,%2,%3}, {%4,%5,%6,%7}, {%8,%9}, {%0,%1,%2,%3};"
        : "+f"(c[0]), "+f"(c[1]), "+f"(c[2]), "+f"(c[3])
        : "r"(a[0]), "r"(a[1]), "r"(a[2]), "r"(a[3]), "r"(b[0]), "r"(b[1]));
}

__device__ __forceinline__ void cp_async16(unsigned int smem_addr, const void* gptr) {
    asm volatile("cp.async.cg.shared.global [%0], [%1], 16;\n"
                 :: "r"(smem_addr), "l"(gptr));
}

// ---------------- gather subsampled query tokens ----------------
__global__ void gather_q_kernel(const float* __restrict__ x, float* __restrict__ xs)
{
    int idx = blockIdx.x * blockDim.x + threadIdx.x;
    int row = idx >> 6;
    int f   = idx & 63;
    int b = row / NQ;
    int i = row - b * NQ;
    int src;
    if (i < 256) {
        int r = i >> 4, c = i & 15;
        src = (r * 2) * 32 + c * 2;
    } else {
        int j = i - 256;
        int r = j >> 3, c = j & 7;
        src = 1024 + (r * 2) * 16 + c * 2;
    }
    const float4* xp = (const float4*)x;
    float4* op = (float4*)xs;
    op[(size_t)row * 64 + f] = xp[((size_t)b * NTOK + src) * 64 + f];
}

// ---- tf32 GEMM, C = A(MxK)*B(NxK)^T, fused BN col-stats, flexible epilogue ----
// mode 0: D0 row-major MxN        (P projection)
// mode 1: KV split head-major     (D0=Kt [b,h,1280,32], D1=Vt [b,h,1280,64])
// mode 2: Q head-major            (D0=Qt [b,h,320,32])
#define LDSW 36   // 32 + 4 pad

__global__ __launch_bounds__(256, 2)
void gemm_tf32_stats(const float* __restrict__ A, const float* __restrict__ B,
                     float* __restrict__ D0, float* __restrict__ D1,
                     float* __restrict__ psum, float* __restrict__ psq,
                     int M, int N, int K, int mode)
{
    __shared__ float As[128 * LDSW];
    __shared__ float Bs[128 * LDSW];

    int tid = threadIdx.x;
    int bm = blockIdx.y * 128, bn = blockIdx.x * 128;
    int wid = tid >> 5, lane = tid & 31;
    int wm = (wid >> 1) << 5;
    int wn = (wid & 1) << 6;
    int gid = lane >> 2, tg = lane & 3;

    float acc[2][8][4];
#pragma unroll
    for (int im = 0; im < 2; im++)
#pragma unroll
        for (int j = 0; j < 8; j++)
#pragma unroll
            for (int r = 0; r < 4; r++) acc[im][j][r] = 0.f;

    unsigned int sA = (unsigned int)__cvta_generic_to_shared(As);
    unsigned int sB = (unsigned int)__cvta_generic_to_shared(Bs);

    int nch = K >> 5;

#pragma unroll
    for (int i = 0; i < 4; i++) {
        int idx = i * 256 + tid, row = idx >> 3, c4 = idx & 7;
        unsigned int off = (unsigned int)((row * LDSW + c4 * 4) << 2);
        cp_async16(sA + off, A + (size_t)(bm + row) * K + c4 * 4);
        cp_async16(sB + off, B + (size_t)(bn + row) * K + c4 * 4);
    }
    asm volatile("cp.async.commit_group;\n");

    for (int c = 0; c < nch; c++) {
        asm volatile("cp.async.wait_group 0;\n");
        __syncthreads();

#pragma unroll
        for (int s = 0; s < 4; s++) {
            int kk = s * 8;
            unsigned int af[2][4], bf[8][2];
#pragma unroll
            for (int im = 0; im < 2; im++) {
                const float* p = As + (wm + im * 16 + gid) * LDSW + kk + tg;
                af[im][0] = f2tf(p[0]);
                af[im][1] = f2tf(p[8 * LDSW]);
                af[im][2] = f2tf(p[4]);
                af[im][3] = f2tf(p[8 * LDSW + 4]);
            }
#pragma unroll
            for (int j = 0; j < 8; j++) {
                const float* p = Bs + (wn + j * 8 + gid) * LDSW + kk + tg;
                bf[j][0] = f2tf(p[0]);
                bf[j][1] = f2tf(p[4]);
            }
#pragma unroll
            for (int im = 0; im < 2; im++)
#pragma unroll
                for (int j = 0; j < 8; j++)
                    mma8(acc[im][j], af[im], bf[j]);
        }

        __syncthreads();
        if (c + 1 < nch) {
            int k0 = (c + 1) << 5;
#pragma unroll
            for (int i = 0; i < 4; i++) {
                int idx = i * 256 + tid, row = idx >> 3, c4 = idx & 7;
                unsigned int off = (unsigned int)((row * LDSW + c4 * 4) << 2);
                cp_async16(sA + off, A + (size_t)(bm + row) * K + k0 + c4 * 4);
                cp_async16(sB + off, B + (size_t)(bn + row) * K + k0 + c4 * 4);
            }
            asm volatile("cp.async.commit_group;\n");
        }
    }

    __syncthreads();   // all mma reads of As/Bs done (As reused for stats below)

    // ---------- stores ----------
#pragma unroll
    for (int im = 0; im < 2; im++) {
        int r0 = bm + wm + im * 16 + gid;
#pragma unroll
        for (int j = 0; j < 8; j++) {
            int c0 = bn + wn + j * 8 + tg * 2;
            float2 v0 = make_float2(acc[im][j][0], acc[im][j][1]);
            float2 v1 = make_float2(acc[im][j][2], acc[im][j][3]);
            if (mode == 0) {
                *(float2*)&D0[(size_t)r0 * N + c0]       = v0;
                *(float2*)&D0[(size_t)(r0 + 8) * N + c0] = v1;
            } else if (mode == 1) {
                int h = c0 / 96, jj = c0 % 96;
                int b = r0 / NTOK, n0 = r0 - b * NTOK;   // 1280%128==0: rows r0,r0+8 same b
                size_t base = ((size_t)(b * NH + h) * NTOK + n0);
                if (jj < 32) {
                    float* kp = D0 + base * KD + jj;
                    *(float2*)kp            = v0;
                    *(float2*)(kp + 8 * KD) = v1;
                } else {
                    float* vp = D1 + base * DV + (jj - 32);
                    *(float2*)vp            = v0;
                    *(float2*)(vp + 8 * DV) = v1;
                }
            } else {  // mode 2 (NQ=320 not 128-aligned: resolve each row)
                int h = c0 >> 5, jj = c0 & 31;
                int b0 = r0 / NQ, q0r = r0 - b0 * NQ;
                int r1 = r0 + 8;
                int b1 = r1 / NQ, q1r = r1 - b1 * NQ;
                *(float2*)&D0[((size_t)(b0 * NH + h) * NQ + q0r) * KD + jj] = v0;
                *(float2*)&D0[((size_t)(b1 * NH + h) * NQ + q1r) * KD + jj] = v1;
            }
        }
    }

    // ---------- fused BN column stats (deterministic) ----------
    float cs[16], cq[16];
#pragma unroll
    for (int j = 0; j < 8; j++) {
#pragma unroll
        for (int r = 0; r < 2; r++) {
            float s = 0.f, q2 = 0.f;
#pragma unroll
            for (int im = 0; im < 2; im++) {
                float x0 = acc[im][j][r];
                float x1 = acc[im][j][r + 2];
                s  += x0 + x1;
                q2 += x0 * x0 + x1 * x1;
            }
            cs[j * 2 + r] = s;
            cq[j * 2 + r] = q2;
        }
    }
#pragma unroll
    for (int m = 4; m <= 16; m <<= 1) {
#pragma unroll
        for (int i = 0; i < 16; i++) {
            cs[i] += __shfl_xor_sync(0xffffffffu, cs[i], m);
            cq[i] += __shfl_xor_sync(0xffffffffu, cq[i], m);
        }
    }
    float* st = As;   // reuse: [4][128] sums, then [4][128] sumsq at +512
    if (gid == 0) {
        int wmi = wid >> 1;
#pragma unroll
        for (int i = 0; i < 16; i++) {
            int cl = wn + (i >> 1) * 8 + tg * 2 + (i & 1);
            st[wmi * 128 + cl]       = cs[i];
            st[512 + wmi * 128 + cl] = cq[i];
        }
    }
    __syncthreads();
    if (tid < 128) {
        float s  = st[tid] + st[128 + tid] + st[256 + tid] + st[384 + tid];
        float q2 = st[512 + tid] + st[640 + tid] + st[768 + tid] + st[896 + tid];
        psum[(size_t)blockIdx.y * N + bn + tid] = s;
        psq [(size_t)blockIdx.y * N + bn + tid] = q2;
    }
}

// ---------------- BN finalize over R block-row partials ----------------
__global__ void bn_finalize2(const float* __restrict__ psum, const float* __restrict__ psq,
                             const float* __restrict__ g, const float* __restrict__ bta,
                             int C, int R, float invM,
                             float* __restrict__ a, float* __restrict__ sh)
{
    int tx = threadIdx.x, ty = threadIdx.y;
    int col = blockIdx.x * 32 + tx;
    float s = 0.f, q2 = 0.f;
    for (int r = ty; r < R; r += 8) {
        s  += psum[(size_t)r * C + col];
        q2 += psq[(size_t)r * C + col];
    }
    __shared__ float ss[8][32], sq[8][32];
    ss[ty][tx] = s; sq[ty][tx] = q2;
    __syncthreads();
    if (ty == 0) {
        float ts = 0.f, tq = 0.f;
#pragma unroll
        for (int y = 0; y < 8; y++) { ts += ss[y][tx]; tq += sq[y][tx]; }
        float mean = ts * invM;
        float var = tq * invM - mean * mean;
        float aa = g[col] * rsqrtf(var + EPSBN);
        a[col] = aa;
        sh[col] = bta[col] - mean * aa;
    }
}

// ---------------- tensor-core flash attention on RAW K/V ----------------
// K scale folded into Q; K shift cancels in softmax; V affine in epilogue.
#define SM_KSTR 36
#define SM_VSTR 72
#define SM_PSTR 68
#define SM_BUF  6912
#define SM_POFF 13824
#define SM_TOTALF (SM_POFF + 4 * 16 * SM_PSTR)   // 18176 floats = 72704 B

__device__ __forceinline__ void stage_tile(unsigned int smem_bytes,
                                           const float* __restrict__ Kg,
                                           const float* __restrict__ Vg,
                                           int kt, int tid)
{
    const float4* Ks = (const float4*)(Kg + (size_t)kt * 64 * KD);
    const float4* Vs = (const float4*)(Vg + (size_t)kt * 64 * DV);
#pragma unroll
    for (int i = 0; i < 4; i++) {
        int idx = i * 128 + tid; int r = idx >> 3, f = idx & 7;
        cp_async16(smem_bytes + (unsigned int)((r * SM_KSTR + f * 4) << 2), Ks + r * 8 + f);
    }
#pragma unroll
    for (int i = 0; i < 8; i++) {
        int idx = i * 128 + tid; int r = idx >> 4, f = idx & 15;
        cp_async16(smem_bytes + (unsigned int)((2304 + r * SM_VSTR + f * 4) << 2), Vs + r * 16 + f);
    }
}

__device__ __forceinline__ float hswish(float x) {
    return x * fminf(fmaxf(x + 3.f, 0.f), 6.f) * (1.f / 6.f);
}

__global__ __launch_bounds__(128)
void attn_tc(const float* __restrict__ Qt, const float* __restrict__ Kt,
             const float* __restrict__ Vt,
             const float* __restrict__ aQ, const float* __restrict__ shQ,
             const float* __restrict__ aKV, const float* __restrict__ shKV,
             float* __restrict__ O)
{
    extern __shared__ float smf[];
    int tid  = threadIdx.x;
    int warp = tid >> 5, lane = tid & 31;
    int gid = lane >> 2, tg = lane & 3;
    int qt = blockIdx.x, h = blockIdx.y, b = blockIdx.z;
    int bh = b * NH + h;

    const float* Kg = Kt + (size_t)bh * NTOK * KD;
    const float* Vg = Vt + (size_t)bh * NTOK * DV;
    unsigned int smb = (unsigned int)__cvta_generic_to_shared(smf);
    float* Pw = smf + SM_POFF + warp * (16 * SM_PSTR);

    // Q fragments: raw q -> (q*aQ + shQ) * aK * SCALE*log2e
    int q0 = qt * 64 + warp * 16;
    const float* Qg  = Qt + ((size_t)bh * NQ + q0) * KD;
    const float* aQh = aQ + h * KD;
    const float* sQh = shQ + h * KD;
    const float* aKh = aKV + h * 96;
    const float SC = SCALE_ATTN * LOG2E;
    unsigned int qa[4][4];
#pragma unroll
    for (int kc = 0; kc < 4; kc++) {
        int c0 = kc * 8 + tg, c1 = c0 + 4;
        float m0 = __ldg(aQh + c0) * __ldg(aKh + c0) * SC;
        float o0 = __ldg(sQh + c0) * __ldg(aKh + c0) * SC;
        float m1 = __ldg(aQh + c1) * __ldg(aKh + c1) * SC;
        float o1 = __ldg(sQh + c1) * __ldg(aKh + c1) * SC;
        qa[kc][0] = f2tf(__ldg(Qg + gid * KD + c0)       * m0 + o0);
        qa[kc][1] = f2tf(__ldg(Qg + (gid + 8) * KD + c0) * m0 + o0);
        qa[kc][2] = f2tf(__ldg(Qg + gid * KD + c1)       * m1 + o1);
        qa[kc][3] = f2tf(__ldg(Qg + (gid + 8) * KD + c1) * m1 + o1);
    }

    float acc[8][4];
#pragma unroll
    for (int nt = 0; nt < 8; nt++)
#pragma unroll
        for (int r = 0; r < 4; r++) acc[nt][r] = 0.f;
    float l0 = 0.f, l1 = 0.f;

    stage_tile(smb, Kg, Vg, 0, tid);
    asm volatile("cp.async.commit_group;\n");

    const int NKT = NTOK / 64;   // 20
    for (int kt = 0; kt < NKT; kt++) {
        if (kt + 1 < NKT) {
            stage_tile(smb + ((kt + 1) & 1) * SM_BUF * 4, Kg, Vg, kt + 1, tid);
            asm volatile("cp.async.commit_group;\n");
            asm volatile("cp.async.wait_group 1;\n");
        } else {
            asm volatile("cp.async.wait_group 0;\n");
        }
        __syncthreads();

        const float* Ksm = smf + (kt & 1) * SM_BUF;
        const float* Vsm = Ksm + 2304;

#pragma unroll
        for (int nt = 0; nt < 8; nt++) {
            float c[4] = {0.f, 0.f, 0.f, 0.f};
#pragma unroll
            for (int kc = 0; kc < 4; kc++) {
                unsigned int bb[2];
                const float* kp = Ksm + (nt * 8 + gid) * SM_KSTR + kc * 8 + tg;
                bb[0] = f2tf(kp[0]);
                bb[1] = f2tf(kp[4]);
                mma8(c, qa[kc], bb);
            }
            float p0 = ex2f(c[0]), p1 = ex2f(c[1]);
            float p2 = ex2f(c[2]), p3 = ex2f(c[3]);
            l0 += p0 + p1;
            l1 += p2 + p3;
            *(float2*)&Pw[gid * SM_PSTR + nt * 8 + 2 * tg]       = make_float2(p0, p1);
            *(float2*)&Pw[(gid + 8) * SM_PSTR + nt * 8 + 2 * tg] = make_float2(p2, p3);
        }
        __syncwarp();

#pragma unroll
        for (int kc = 0; kc < 8; kc++) {
            unsigned int pa[4];
            pa[0] = f2tf(Pw[gid * SM_PSTR + kc * 8 + tg]);
            pa[1] = f2tf(Pw[(gid + 8) * SM_PSTR + kc * 8 + tg]);
            pa[2] = f2tf(Pw[gid * SM_PSTR + kc * 8 + tg + 4]);
            pa[3] = f2tf(Pw[(gid + 8) * SM_PSTR + kc * 8 + tg + 4]);
#pragma unroll
            for (int nt = 0; nt < 8; nt++) {
                unsigned int vb[2];
                const float* vp = Vsm + (kc * 8 + tg) * SM_VSTR + nt * 8 + gid;
                vb[0] = f2tf(vp[0]);
                vb[1] = f2tf(vp[4 * SM_VSTR]);
                mma8(acc[nt], pa, vb);
            }
        }
        __syncthreads();
    }

    l0 += __shfl_xor_sync(0xffffffffu, l0, 1);
    l0 += __shfl_xor_sync(0xffffffffu, l0, 2);
    l1 += __shfl_xor_sync(0xffffffffu, l1, 1);
    l1 += __shfl_xor_sync(0xffffffffu, l1, 2);
    float inv0 = 1.f / l0, inv1 = 1.f / l1;

    // epilogue: V BN-affine + hard-swish
    const float* aVh = aKV + h * 96 + 32;
    const float* sVh = shKV + h * 96 + 32;
    float* Ob = O + ((size_t)(b * NQ + q0)) * DHD + h * DV;
#pragma unroll
    for (int nt = 0; nt < 8; nt++) {
        int c0 = nt * 8 + 2 * tg;
        float va0 = __ldg(aVh + c0), va1 = __ldg(aVh + c0 + 1);
        float vs0 = __ldg(sVh + c0), vs1 = __ldg(sVh + c0 + 1);
        float v0 = acc[nt][0] * inv0 * va0 + vs0;
        float v1 = acc[nt][1] * inv0 * va1 + vs1;
        float v2 = acc[nt][2] * inv1 * va0 + vs0;
        float v3 = acc[nt][3] * inv1 * va1 + vs1;
        *(float2*)&Ob[(size_t)gid * DHD + c0]       = make_float2(hswish(v0), hswish(v1));
        *(float2*)&Ob[(size_t)(gid + 8) * DHD + c0] = make_float2(hswish(v2), hswish(v3));
    }
}

// ---------------- final BN-affine into d_out ----------------
__global__ void apply_affine_out(const float* __restrict__ Y,
                                 const float* __restrict__ a, const float* __restrict__ sh,
                                 float* __restrict__ out)
{
    int idx = blockIdx.x * blockDim.x + threadIdx.x;
    int c4 = idx & 127;
    float4 y = ((const float4*)Y)[idx];
    float4 aa = ((const float4*)a)[c4];
    float4 ss = ((const float4*)sh)[c4];
    float4 r;
    r.x = y.x * aa.x + ss.x;
    r.y = y.y * aa.y + ss.y;
    r.z = y.z * aa.z + ss.z;
    r.w = y.w * aa.w + ss.w;
    ((float4*)out)[idx] = r;
}

// ---------------- launch ----------------
extern "C" void kernel_launch(void* const* d_in, const int* in_sizes, int n_in,
                              void* d_out, int out_size)
{
    const float* x   = (const float*)d_in[0];
    const float* Wkv = (const float*)d_in[1];
    const float* gkv = (const float*)d_in[2];
    const float* bkv = (const float*)d_in[3];
    const float* Wq  = (const float*)d_in[4];
    const float* gq  = (const float*)d_in[5];
    const float* bq  = (const float*)d_in[6];
    const float* Wp  = (const float*)d_in[7];
    const float* gp  = (const float*)d_in[8];
    const float* bp  = (const float*)d_in[9];
    float* out = (float*)d_out;

    float *sXsub, *sO, *sP, *Qt, *Kt, *Vt;
    float *psKV, *pqKV, *psQ, *pqQ, *psP, *pqP;
    float *aKV, *shKV, *aQ, *shQ, *aP, *shP;
    cudaGetSymbolAddress((void**)&sXsub, g_sXsub);
    cudaGetSymbolAddress((void**)&sO,    g_sO);
    cudaGetSymbolAddress((void**)&sP,    g_sP);
    cudaGetSymbolAddress((void**)&Qt,    g_Qt);
    cudaGetSymbolAddress((void**)&Kt,    g_Kt);
    cudaGetSymbolAddress((void**)&Vt,    g_Vt);
    cudaGetSymbolAddress((void**)&psKV,  g_psumKV);
    cudaGetSymbolAddress((void**)&pqKV,  g_psqKV);
    cudaGetSymbolAddress((void**)&psQ,   g_psumQ);
    cudaGetSymbolAddress((void**)&pqQ,   g_psqQ);
    cudaGetSymbolAddress((void**)&psP,   g_psumP);
    cudaGetSymbolAddress((void**)&pqP,   g_psqP);
    cudaGetSymbolAddress((void**)&aKV,   g_aKV);
    cudaGetSymbolAddress((void**)&shKV,  g_shKV);
    cudaGetSymbolAddress((void**)&aQ,    g_aQ);
    cudaGetSymbolAddress((void**)&shQ,   g_shQ);
    cudaGetSymbolAddress((void**)&aP,    g_aP);
    cudaGetSymbolAddress((void**)&shP,   g_shP);

    static bool attr_set = false;
    if (!attr_set) {
        cudaFuncSetAttribute(attn_tc, cudaFuncAttributeMaxDynamicSharedMemorySize,
                             SM_TOTALF * 4);
        attr_set = true;
    }

    // 1. gather subsampled query tokens
    gather_q_kernel<<<(M_Q * (CIN / 4)) / 256, 256>>>(x, sXsub);

    // 2. projections: head-major outputs + fused BN stats
    gemm_tf32_stats<<<dim3(CKV / 128, M_KV / 128), 256>>>(
        x, Wkv, Kt, Vt, psKV, pqKV, M_KV, CKV, CIN, 1);
    gemm_tf32_stats<<<dim3(CQ / 128, M_Q / 128), 256>>>(
        sXsub, Wq, Qt, nullptr, psQ, pqQ, M_Q, CQ, CIN, 2);

    // 3. BN finalize
    bn_finalize2<<<CKV / 32, dim3(32, 8)>>>(psKV, pqKV, gkv, bkv, CKV, M_KV / 128,
                                            1.f / M_KV, aKV, shKV);
    bn_finalize2<<<CQ / 32, dim3(32, 8)>>>(psQ, pqQ, gq, bq, CQ, M_Q / 128,
                                           1.f / M_Q, aQ, shQ);

    // 4. attention on raw K/V (affines folded; hard_swish fused)
    attn_tc<<<dim3(NQ / 64, NH, BB), 128, SM_TOTALF * 4>>>(
        Qt, Kt, Vt, aQ, shQ, aKV, shKV, sO);

    // 5. output projection + BN
    gemm_tf32_stats<<<dim3(COUT / 128, M_Q / 128), 256>>>(
        sO, Wp, sP, nullptr, psP, pqP, M_Q, COUT, DHD, 0);
    bn_finalize2<<<COUT / 32, dim3(32, 8)>>>(psP, pqP, gp, bp, COUT, M_Q / 128,
                                             1.f / M_Q, aP, shP);
    apply_affine_out<<<(M_Q * COUT / 4) / 256, 256>>>(sP, aP, shP, out);
}

// round 14
// speedup vs baseline: 3.5042x; 1.1543x over previous
#include <cuda_runtime.h>
#include <cuda_bf16.h>
#include <cstdint>
#include <math.h>

// ---------------- problem constants ----------------
#define BB 64
#define NTOK 1280
#define NQ 320
#define CIN 256
#define CKV 768
#define CQ 256
#define DHD 512
#define COUT 512
#define NH 8
#define KD 32
#define DV 64
#define EPSBN 1e-5f
#define SCALE_ATTN 0.17677669529663687f
#define LOG2E 1.4426950408889634f

#define M_KV (BB*NTOK)   // 81920
#define M_Q  (BB*NQ)     // 20480

// ---------------- device scratch ----------------
__device__ float g_sXsub[(size_t)M_Q * CIN];
__device__ float g_sO[(size_t)M_Q * DHD];
__device__ float g_sP[(size_t)M_Q * COUT];
__device__ float g_Qt[(size_t)BB * NH * NQ * KD];     // raw fp32 Q head-major
__device__ float g_Kt[(size_t)BB * NH * NTOK * KD];   // tf32, col-permuted
__device__ float g_Vt[(size_t)BB * NH * NTOK * DV];   // tf32, natural
__device__ float g_Wkvp[CKV * CIN];                   // tf32 permuted weights
__device__ float g_Wqp[CQ * CIN];
__device__ float g_Wpp[COUT * DHD];
__device__ float g_psumKV[640 * CKV], g_psqKV[640 * CKV];
__device__ float g_psumQ[160 * CQ],   g_psqQ[160 * CQ];
__device__ float g_psumP[160 * COUT], g_psqP[160 * COUT];
__device__ float g_aKV[CKV], g_shKV[CKV];
__device__ float g_aQ[CQ],  g_shQ[CQ];
__device__ float g_aP[COUT], g_shP[COUT];

// ---------------- helpers ----------------
__device__ __forceinline__ unsigned int f2tf(float f) {
    unsigned int r;
    asm("cvt.rna.tf32.f32 %0, %1;" : "=r"(r) : "f"(f));
    return r;
}
__device__ __forceinline__ float tf32f(float f) {
    unsigned int r;
    asm("cvt.rna.tf32.f32 %0, %1;" : "=r"(r) : "f"(f));
    return __uint_as_float(r);
}
__device__ __forceinline__ float ex2f(float x) {
    float r;
    asm("ex2.approx.f32 %0, %1;" : "=f"(r) : "f"(x));
    return r;
}
__device__ __forceinline__ int perm8i(int j) {   // pair (t,t+4) -> adjacent slots
    return (j < 4) ? 2 * j : 2 * (j - 4) + 1;
}
__device__ __forceinline__ void mma8(float* c, const unsigned int* a, const unsigned int* b) {
    asm volatile(
        "mma.sync.aligned.m16n8k8.row.col.f32.tf32.tf32.f32 "
        "{%0,%1,%2,%3}, {%4,%5,%6,%7}, {%8,%9}, {%0,%1,%2,%3};"
        : "+f"(c[0]), "+f"(c[1]), "+f"(c[2]), "+f"(c[3])
        : "r"(a[0]), "r"(a[1]), "r"(a[2]), "r"(a[3]), "r"(b[0]), "r"(b[1]));
}
__device__ __forceinline__ void cp_async16(unsigned int smem_addr, const void* gptr) {
    asm volatile("cp.async.cg.shared.global [%0], [%1], 16;\n"
                 :: "r"(smem_addr), "l"(gptr));
}

// ---------------- weight pre-permute (fp32 -> tf32 bits, k-pair permuted) ----------------
__global__ void permute_w(const float* __restrict__ in, float* __restrict__ out,
                          int K, int total)
{
    int i = blockIdx.x * 256 + threadIdx.x;
    if (i >= total) return;
    int row = i / K, k = i - row * K;
    int pos = (k & ~7) + perm8i(k & 7);
    out[row * K + pos] = tf32f(in[i]);
}

// ---------------- gather subsampled query tokens ----------------
__global__ void gather_q_kernel(const float* __restrict__ x, float* __restrict__ xs)
{
    int idx = blockIdx.x * blockDim.x + threadIdx.x;
    int row = idx >> 6;
    int f   = idx & 63;
    int b = row / NQ;
    int i = row - b * NQ;
    int src;
    if (i < 256) {
        int r = i >> 4, c = i & 15;
        src = (r * 2) * 32 + c * 2;
    } else {
        int j = i - 256;
        int r = j >> 3, c = j & 7;
        src = 1024 + (r * 2) * 16 + c * 2;
    }
    const float4* xp = (const float4*)x;
    float4* op = (float4*)xs;
    op[(size_t)row * 64 + f] = xp[((size_t)b * NTOK + src) * 64 + f];
}

// ---- tf32 GEMM v2: raw-fp32 A, pre-permuted-tf32 B, double-buffered cp.async ----
// mode 0: D0 row-major MxN (P proj)   mode 1: K perm-tf32 + V tf32 head-major
// mode 2: Q raw fp32 head-major
#define GA_STR 36
#define GB_STR 40
#define GA_TILE (128*GA_STR)   // 4608
#define GB_TILE (128*GB_STR)   // 5120
#define G_SMEMF (2*GA_TILE + 2*GB_TILE)   // 19456 floats = 77824 B

__global__ __launch_bounds__(256, 2)
void gemm_tf32_stats(const float* __restrict__ A, const float* __restrict__ Bp,
                     float* __restrict__ D0, float* __restrict__ D1,
                     float* __restrict__ psum, float* __restrict__ psq,
                     int M, int N, int K, int mode)
{
    extern __shared__ float smf[];
    float* Abuf[2] = { smf, smf + GA_TILE };
    float* Bbuf[2] = { smf + 2 * GA_TILE, smf + 2 * GA_TILE + GB_TILE };
    unsigned int smb = (unsigned int)__cvta_generic_to_shared(smf);

    int tid = threadIdx.x;
    int bm = blockIdx.y * 128, bn = blockIdx.x * 128;
    int wid = tid >> 5, lane = tid & 31;
    int wm = (wid >> 1) << 5;
    int wn = (wid & 1) << 6;
    int gid = lane >> 2, tg = lane & 3;

    float acc[2][8][4];
#pragma unroll
    for (int im = 0; im < 2; im++)
#pragma unroll
        for (int j = 0; j < 8; j++)
#pragma unroll
            for (int r = 0; r < 4; r++) acc[im][j][r] = 0.f;

    int nch = K >> 5;
    int srow = tid >> 3, sc4 = tid & 7;   // 32 rows x 8 chunks covered per 256-thr pass x4

    // stage chunk 0 into buffer 0
#pragma unroll
    for (int i = 0; i < 4; i++) {
        int row = srow + i * 32;
        cp_async16(smb + (unsigned int)(((row * GA_STR + sc4 * 4)) << 2),
                   A + (size_t)(bm + row) * K + sc4 * 4);
        cp_async16(smb + (unsigned int)(((2 * GA_TILE + row * GB_STR + sc4 * 4)) << 2),
                   Bp + (size_t)(bn + row) * K + sc4 * 4);
    }
    asm volatile("cp.async.commit_group;\n");

    for (int c = 0; c < nch; c++) {
        if (c + 1 < nch) {
            int k0 = (c + 1) << 5;
            int bsel = (c + 1) & 1;
            unsigned int aoff = bsel ? GA_TILE : 0u;
            unsigned int boff = 2 * GA_TILE + (bsel ? GB_TILE : 0u);
#pragma unroll
            for (int i = 0; i < 4; i++) {
                int row = srow + i * 32;
                cp_async16(smb + (unsigned int)((aoff + row * GA_STR + sc4 * 4) << 2),
                           A + (size_t)(bm + row) * K + k0 + sc4 * 4);
                cp_async16(smb + (unsigned int)((boff + row * GB_STR + sc4 * 4) << 2),
                           Bp + (size_t)(bn + row) * K + k0 + sc4 * 4);
            }
            asm volatile("cp.async.commit_group;\n");
            asm volatile("cp.async.wait_group 1;\n");
        } else {
            asm volatile("cp.async.wait_group 0;\n");
        }
        __syncthreads();

        const float* Ar = Abuf[c & 1];
        const float* Br = Bbuf[c & 1];

#pragma unroll
        for (int s = 0; s < 4; s++) {
            int kk = s * 8;
            unsigned int af[2][4], bf[8][2];
#pragma unroll
            for (int im = 0; im < 2; im++) {
                const float* p = Ar + (wm + im * 16 + gid) * GA_STR + kk + tg;
                af[im][0] = f2tf(p[0]);
                af[im][1] = f2tf(p[8 * GA_STR]);
                af[im][2] = f2tf(p[4]);
                af[im][3] = f2tf(p[8 * GA_STR + 4]);
            }
#pragma unroll
            for (int j = 0; j < 8; j++) {
                float2 v = *(const float2*)(Br + (wn + j * 8 + gid) * GB_STR + kk + tg * 2);
                bf[j][0] = __float_as_uint(v.x);
                bf[j][1] = __float_as_uint(v.y);
            }
#pragma unroll
            for (int im = 0; im < 2; im++)
#pragma unroll
                for (int j = 0; j < 8; j++)
                    mma8(acc[im][j], af[im], bf[j]);
        }
        __syncthreads();   // buffer (c&1) free for restage at iter c+1
    }

    // ---------- stores ----------
#pragma unroll
    for (int im = 0; im < 2; im++) {
        int r0 = bm + wm + im * 16 + gid;
#pragma unroll
        for (int j = 0; j < 8; j++) {
            int c0 = bn + wn + j * 8 + tg * 2;
            if (mode == 0) {
                *(float2*)&D0[(size_t)r0 * N + c0] = make_float2(acc[im][j][0], acc[im][j][1]);
                *(float2*)&D0[(size_t)(r0 + 8) * N + c0] = make_float2(acc[im][j][2], acc[im][j][3]);
            } else if (mode == 1) {
                int h = c0 / 96, jj = c0 % 96;
                int b = r0 / NTOK, n0 = r0 - b * NTOK;
                size_t base = ((size_t)(b * NH + h) * NTOK + n0);
                if (jj < 32) {
                    // permuted tf32 K
                    int pe = (jj & ~7) + perm8i(jj & 7);
                    int po = (jj & ~7) + perm8i((jj + 1) & 7);
                    float* kp = D0 + base * KD;
                    kp[pe] = tf32f(acc[im][j][0]);
                    kp[po] = tf32f(acc[im][j][1]);
                    kp[8 * KD + pe] = tf32f(acc[im][j][2]);
                    kp[8 * KD + po] = tf32f(acc[im][j][3]);
                } else {
                    float* vp = D1 + base * DV + (jj - 32);
                    *(float2*)vp = make_float2(tf32f(acc[im][j][0]), tf32f(acc[im][j][1]));
                    *(float2*)(vp + 8 * DV) = make_float2(tf32f(acc[im][j][2]), tf32f(acc[im][j][3]));
                }
            } else {
                int h = c0 >> 5, jj = c0 & 31;
                int b0 = r0 / NQ, q0r = r0 - b0 * NQ;
                int r1 = r0 + 8;
                int b1 = r1 / NQ, q1r = r1 - b1 * NQ;
                *(float2*)&D0[((size_t)(b0 * NH + h) * NQ + q0r) * KD + jj] =
                    make_float2(acc[im][j][0], acc[im][j][1]);
                *(float2*)&D0[((size_t)(b1 * NH + h) * NQ + q1r) * KD + jj] =
                    make_float2(acc[im][j][2], acc[im][j][3]);
            }
        }
    }

    // ---------- fused BN column stats ----------
    float cs[16], cq[16];
#pragma unroll
    for (int j = 0; j < 8; j++) {
#pragma unroll
        for (int r = 0; r < 2; r++) {
            float s = 0.f, q2 = 0.f;
#pragma unroll
            for (int im = 0; im < 2; im++) {
                float x0 = acc[im][j][r];
                float x1 = acc[im][j][r + 2];
                s += x0 + x1;
                q2 += x0 * x0 + x1 * x1;
            }
            cs[j * 2 + r] = s;
            cq[j * 2 + r] = q2;
        }
    }
#pragma unroll
    for (int m = 4; m <= 16; m <<= 1) {
#pragma unroll
        for (int i = 0; i < 16; i++) {
            cs[i] += __shfl_xor_sync(0xffffffffu, cs[i], m);
            cq[i] += __shfl_xor_sync(0xffffffffu, cq[i], m);
        }
    }
    float* st = smf;
    if (gid == 0) {
        int wmi = wid >> 1;
#pragma unroll
        for (int i = 0; i < 16; i++) {
            int cl = wn + (i >> 1) * 8 + tg * 2 + (i & 1);
            st[wmi * 128 + cl] = cs[i];
            st[512 + wmi * 128 + cl] = cq[i];
        }
    }
    __syncthreads();
    if (tid < 128) {
        float s = st[tid] + st[128 + tid] + st[256 + tid] + st[384 + tid];
        float q2 = st[512 + tid] + st[640 + tid] + st[768 + tid] + st[896 + tid];
        psum[(size_t)blockIdx.y * N + bn + tid] = s;
        psq [(size_t)blockIdx.y * N + bn + tid] = q2;
    }
}

// ---------------- BN finalize ----------------
__global__ void bn_finalize2(const float* __restrict__ psum, const float* __restrict__ psq,
                             const float* __restrict__ g, const float* __restrict__ bta,
                             int C, int R, float invM,
                             float* __restrict__ a, float* __restrict__ sh)
{
    int tx = threadIdx.x, ty = threadIdx.y;
    int col = blockIdx.x * 32 + tx;
    float s = 0.f, q2 = 0.f;
    for (int r = ty; r < R; r += 16) {
        s  += psum[(size_t)r * C + col];
        q2 += psq[(size_t)r * C + col];
    }
    __shared__ float ss[16][32], sq[16][32];
    ss[ty][tx] = s; sq[ty][tx] = q2;
    __syncthreads();
    if (ty == 0) {
        float ts = 0.f, tq = 0.f;
#pragma unroll
        for (int y = 0; y < 16; y++) { ts += ss[y][tx]; tq += sq[y][tx]; }
        float mean = ts * invM;
        float var = tq * invM - mean * mean;
        float aa = g[col] * rsqrtf(var + EPSBN);
        a[col] = aa;
        sh[col] = bta[col] - mean * aa;
    }
}

// ---------------- tensor-core flash attention (tf32-ready K/V/P) ----------------
#define SM_KSTR 40
#define SM_VSTR 72
#define SM_PSTR 72
#define SM_BUF  (64*SM_KSTR + 64*SM_VSTR)          // 7168 floats
#define SM_POFF (2*SM_BUF)                          // 14336
#define SM_TOTALF (SM_POFF + 4 * 16 * SM_PSTR)      // 18944 floats = 75776 B

__device__ __forceinline__ void stage_tile(unsigned int smem_bytes,
                                           const float* __restrict__ Kg,
                                           const float* __restrict__ Vg,
                                           int kt, int tid)
{
    const float4* Ks = (const float4*)(Kg + (size_t)kt * 64 * KD);
    const float4* Vs = (const float4*)(Vg + (size_t)kt * 64 * DV);
#pragma unroll
    for (int i = 0; i < 4; i++) {
        int idx = i * 128 + tid; int r = idx >> 3, f = idx & 7;
        cp_async16(smem_bytes + (unsigned int)((r * SM_KSTR + f * 4) << 2), Ks + r * 8 + f);
    }
#pragma unroll
    for (int i = 0; i < 8; i++) {
        int idx = i * 128 + tid; int r = idx >> 4, f = idx & 15;
        cp_async16(smem_bytes + (unsigned int)((64 * SM_KSTR + r * SM_VSTR + f * 4) << 2),
                   Vs + r * 16 + f);
    }
}

__device__ __forceinline__ float hswish(float x) {
    return x * fminf(fmaxf(x + 3.f, 0.f), 6.f) * (1.f / 6.f);
}

__global__ __launch_bounds__(128)
void attn_tc(const float* __restrict__ Qt, const float* __restrict__ Kt,
             const float* __restrict__ Vt,
             const float* __restrict__ aQ, const float* __restrict__ shQ,
             const float* __restrict__ aKV, const float* __restrict__ shKV,
             float* __restrict__ O)
{
    extern __shared__ float smf[];
    int tid  = threadIdx.x;
    int warp = tid >> 5, lane = tid & 31;
    int gid = lane >> 2, tg = lane & 3;
    int qt = blockIdx.x, h = blockIdx.y, b = blockIdx.z;
    int bh = b * NH + h;

    const float* Kg = Kt + (size_t)bh * NTOK * KD;
    const float* Vg = Vt + (size_t)bh * NTOK * DV;
    unsigned int smb = (unsigned int)__cvta_generic_to_shared(smf);
    float* Pw = smf + SM_POFF + warp * (16 * SM_PSTR);

    int q0 = qt * 64 + warp * 16;
    const float* Qg  = Qt + ((size_t)bh * NQ + q0) * KD;
    const float* aQh = aQ + h * KD;
    const float* sQh = shQ + h * KD;
    const float* aKh = aKV + h * 96;
    const float SC = SCALE_ATTN * LOG2E;
    unsigned int qa[4][4];
#pragma unroll
    for (int kc = 0; kc < 4; kc++) {
        int c0 = kc * 8 + tg, c1 = c0 + 4;
        float m0 = __ldg(aQh + c0) * __ldg(aKh + c0) * SC;
        float o0 = __ldg(sQh + c0) * __ldg(aKh + c0) * SC;
        float m1 = __ldg(aQh + c1) * __ldg(aKh + c1) * SC;
        float o1 = __ldg(sQh + c1) * __ldg(aKh + c1) * SC;
        qa[kc][0] = f2tf(__ldg(Qg + gid * KD + c0)       * m0 + o0);
        qa[kc][1] = f2tf(__ldg(Qg + (gid + 8) * KD + c0) * m0 + o0);
        qa[kc][2] = f2tf(__ldg(Qg + gid * KD + c1)       * m1 + o1);
        qa[kc][3] = f2tf(__ldg(Qg + (gid + 8) * KD + c1) * m1 + o1);
    }

    float acc[8][4];
#pragma unroll
    for (int nt = 0; nt < 8; nt++)
#pragma unroll
        for (int r = 0; r < 4; r++) acc[nt][r] = 0.f;
    float l0 = 0.f, l1 = 0.f;

    // permuted P column slots for this thread
    int pe = perm8i(2 * tg), po = perm8i(2 * tg + 1);

    stage_tile(smb, Kg, Vg, 0, tid);
    asm volatile("cp.async.commit_group;\n");

    const int NKT = NTOK / 64;
    for (int kt = 0; kt < NKT; kt++) {
        if (kt + 1 < NKT) {
            stage_tile(smb + ((kt + 1) & 1) * SM_BUF * 4, Kg, Vg, kt + 1, tid);
            asm volatile("cp.async.commit_group;\n");
            asm volatile("cp.async.wait_group 1;\n");
        } else {
            asm volatile("cp.async.wait_group 0;\n");
        }
        __syncthreads();

        const float* Ksm = smf + (kt & 1) * SM_BUF;
        const float* Vsm = Ksm + 64 * SM_KSTR;

#pragma unroll
        for (int nt = 0; nt < 8; nt++) {
            float c[4] = {0.f, 0.f, 0.f, 0.f};
#pragma unroll
            for (int kc = 0; kc < 4; kc++) {
                float2 kv = *(const float2*)(Ksm + (nt * 8 + gid) * SM_KSTR + kc * 8 + tg * 2);
                unsigned int bb[2] = { __float_as_uint(kv.x), __float_as_uint(kv.y) };
                mma8(c, qa[kc], bb);
            }
            float p0 = ex2f(c[0]), p1 = ex2f(c[1]);
            float p2 = ex2f(c[2]), p3 = ex2f(c[3]);
            l0 += p0 + p1;
            l1 += p2 + p3;
            float* pr0 = Pw + gid * SM_PSTR + nt * 8;
            float* pr1 = Pw + (gid + 8) * SM_PSTR + nt * 8;
            pr0[pe] = tf32f(p0); pr0[po] = tf32f(p1);
            pr1[pe] = tf32f(p2); pr1[po] = tf32f(p3);
        }
        __syncwarp();

#pragma unroll
        for (int kc = 0; kc < 8; kc++) {
            float2 pv0 = *(const float2*)(Pw + gid * SM_PSTR + kc * 8 + tg * 2);
            float2 pv1 = *(const float2*)(Pw + (gid + 8) * SM_PSTR + kc * 8 + tg * 2);
            unsigned int pa[4] = { __float_as_uint(pv0.x), __float_as_uint(pv1.x),
                                   __float_as_uint(pv0.y), __float_as_uint(pv1.y) };
#pragma unroll
            for (int nt = 0; nt < 8; nt++) {
                const float* vp = Vsm + (kc * 8 + tg) * SM_VSTR + nt * 8 + gid;
                unsigned int vb[2] = { __float_as_uint(vp[0]),
                                       __float_as_uint(vp[4 * SM_VSTR]) };
                mma8(acc[nt], pa, vb);
            }
        }
        __syncthreads();
    }

    l0 += __shfl_xor_sync(0xffffffffu, l0, 1);
    l0 += __shfl_xor_sync(0xffffffffu, l0, 2);
    l1 += __shfl_xor_sync(0xffffffffu, l1, 1);
    l1 += __shfl_xor_sync(0xffffffffu, l1, 2);
    float inv0 = 1.f / l0, inv1 = 1.f / l1;

    const float* aVh = aKV + h * 96 + 32;
    const float* sVh = shKV + h * 96 + 32;
    float* Ob = O + ((size_t)(b * NQ + q0)) * DHD + h * DV;
#pragma unroll
    for (int nt = 0; nt < 8; nt++) {
        int c0 = nt * 8 + 2 * tg;
        float va0 = __ldg(aVh + c0), va1 = __ldg(aVh + c0 + 1);
        float vs0 = __ldg(sVh + c0), vs1 = __ldg(sVh + c0 + 1);
        float v0 = acc[nt][0] * inv0 * va0 + vs0;
        float v1 = acc[nt][1] * inv0 * va1 + vs1;
        float v2 = acc[nt][2] * inv1 * va0 + vs0;
        float v3 = acc[nt][3] * inv1 * va1 + vs1;
        *(float2*)&Ob[(size_t)gid * DHD + c0]       = make_float2(hswish(v0), hswish(v1));
        *(float2*)&Ob[(size_t)(gid + 8) * DHD + c0] = make_float2(hswish(v2), hswish(v3));
    }
}

// ---------------- final BN-affine into d_out ----------------
__global__ void apply_affine_out(const float* __restrict__ Y,
                                 const float* __restrict__ a, const float* __restrict__ sh,
                                 float* __restrict__ out)
{
    int idx = blockIdx.x * blockDim.x + threadIdx.x;
    int c4 = idx & 127;
    float4 y = ((const float4*)Y)[idx];
    float4 aa = ((const float4*)a)[c4];
    float4 ss = ((const float4*)sh)[c4];
    float4 r;
    r.x = y.x * aa.x + ss.x;
    r.y = y.y * aa.y + ss.y;
    r.z = y.z * aa.z + ss.z;
    r.w = y.w * aa.w + ss.w;
    ((float4*)out)[idx] = r;
}

// ---------------- launch ----------------
extern "C" void kernel_launch(void* const* d_in, const int* in_sizes, int n_in,
                              void* d_out, int out_size)
{
    const float* x   = (const float*)d_in[0];
    const float* Wkv = (const float*)d_in[1];
    const float* gkv = (const float*)d_in[2];
    const float* bkv = (const float*)d_in[3];
    const float* Wq  = (const float*)d_in[4];
    const float* gq  = (const float*)d_in[5];
    const float* bq  = (const float*)d_in[6];
    const float* Wp  = (const float*)d_in[7];
    const float* gp  = (const float*)d_in[8];
    const float* bp  = (const float*)d_in[9];
    float* out = (float*)d_out;

    float *sXsub, *sO, *sP, *Qt, *Kt, *Vt, *Wkvp, *Wqp, *Wpp;
    float *psKV, *pqKV, *psQ, *pqQ, *psP, *pqP;
    float *aKV, *shKV, *aQ, *shQ, *aP, *shP;
    cudaGetSymbolAddress((void**)&sXsub, g_sXsub);
    cudaGetSymbolAddress((void**)&sO,    g_sO);
    cudaGetSymbolAddress((void**)&sP,    g_sP);
    cudaGetSymbolAddress((void**)&Qt,    g_Qt);
    cudaGetSymbolAddress((void**)&Kt,    g_Kt);
    cudaGetSymbolAddress((void**)&Vt,    g_Vt);
    cudaGetSymbolAddress((void**)&Wkvp,  g_Wkvp);
    cudaGetSymbolAddress((void**)&Wqp,   g_Wqp);
    cudaGetSymbolAddress((void**)&Wpp,   g_Wpp);
    cudaGetSymbolAddress((void**)&psKV,  g_psumKV);
    cudaGetSymbolAddress((void**)&pqKV,  g_psqKV);
    cudaGetSymbolAddress((void**)&psQ,   g_psumQ);
    cudaGetSymbolAddress((void**)&pqQ,   g_psqQ);
    cudaGetSymbolAddress((void**)&psP,   g_psumP);
    cudaGetSymbolAddress((void**)&pqP,   g_psqP);
    cudaGetSymbolAddress((void**)&aKV,   g_aKV);
    cudaGetSymbolAddress((void**)&shKV,  g_shKV);
    cudaGetSymbolAddress((void**)&aQ,    g_aQ);
    cudaGetSymbolAddress((void**)&shQ,   g_shQ);
    cudaGetSymbolAddress((void**)&aP,    g_aP);
    cudaGetSymbolAddress((void**)&shP,   g_shP);

    static bool attr_set = false;
    if (!attr_set) {
        cudaFuncSetAttribute(attn_tc, cudaFuncAttributeMaxDynamicSharedMemorySize,
                             SM_TOTALF * 4);
        cudaFuncSetAttribute(gemm_tf32_stats, cudaFuncAttributeMaxDynamicSharedMemorySize,
                             G_SMEMF * 4);
        attr_set = true;
    }

    // 0-3: gather + weight permutes
    gather_q_kernel<<<(M_Q * (CIN / 4)) / 256, 256>>>(x, sXsub);
    permute_w<<<(CKV * CIN + 255) / 256, 256>>>(Wkv, Wkvp, CIN, CKV * CIN);
    permute_w<<<(CQ * CIN + 255) / 256, 256>>>(Wq, Wqp, CIN, CQ * CIN);
    permute_w<<<(COUT * DHD + 255) / 256, 256>>>(Wp, Wpp, DHD, COUT * DHD);

    // 4-5: projections (KV at profiler slot)
    gemm_tf32_stats<<<dim3(CKV / 128, M_KV / 128), 256, G_SMEMF * 4>>>(
        x, Wkvp, Kt, Vt, psKV, pqKV, M_KV, CKV, CIN, 1);
    gemm_tf32_stats<<<dim3(CQ / 128, M_Q / 128), 256, G_SMEMF * 4>>>(
        sXsub, Wqp, Qt, nullptr, psQ, pqQ, M_Q, CQ, CIN, 2);

    // BN finalize
    bn_finalize2<<<CKV / 32, dim3(32, 16)>>>(psKV, pqKV, gkv, bkv, CKV, M_KV / 128,
                                             1.f / M_KV, aKV, shKV);
    bn_finalize2<<<CQ / 32, dim3(32, 16)>>>(psQ, pqQ, gq, bq, CQ, M_Q / 128,
                                            1.f / M_Q, aQ, shQ);

    // attention (tf32-ready K/V; affines folded; hard_swish fused)
    attn_tc<<<dim3(NQ / 64, NH, BB), 128, SM_TOTALF * 4>>>(
        Qt, Kt, Vt, aQ, shQ, aKV, shKV, sO);

    // output projection + BN
    gemm_tf32_stats<<<dim3(COUT / 128, M_Q / 128), 256, G_SMEMF * 4>>>(
        sO, Wpp, sP, nullptr, psP, pqP, M_Q, COUT, DHD, 0);
    bn_finalize2<<<COUT / 32, dim3(32, 16)>>>(psP, pqP, gp, bp, COUT, M_Q / 128,
                                              1.f / M_Q, aP, shP);
    apply_affine_out<<<(M_Q * COUT / 4) / 256, 256>>>(sP, aP, shP, out);
}